// round 9
// baseline (speedup 1.0000x reference)
#include <cuda_runtime.h>
#include <math.h>

// ---------------- problem constants ----------------
#define BB 4
#define HH 256
#define WW 256
#define CC 32
#define NPIX (HH*WW)            // 65536
#define IMG_ELEMS (BB*NPIX*CC)  // 8388608

typedef unsigned long long ull;

// ---------------- device scratch ----------------
__device__ float g_part[BB*256*1056];
__device__ float g_M[BB*1024];
__device__ float g_cmask[BB*CC];
__device__ float g_smask[BB*NPIX];
__device__ float g_kcomb[49*32];
__device__ float g_vg[IMG_ELEMS];
__device__ float g_vspec[IMG_ELEMS];
__device__ float g_tpos[IMG_ELEMS];
__device__ float g_outn[IMG_ELEMS];

__device__ __forceinline__ float gelu_exact(float x) {
    return 0.5f * x * (1.0f + erff(x * 0.70710678118654752f));
}
__device__ __forceinline__ float sigmoidf_(float x) {
    return 1.0f / (1.0f + expf(-x));
}

// ---------------- packed f32x2 helpers ----------------
__device__ __forceinline__ void fma2(ull& c, ull a, ull b) {
    asm("fma.rn.f32x2 %0, %1, %2, %0;" : "+l"(c) : "l"(a), "l"(b));
}
__device__ __forceinline__ ull pk2(float x) {          // {x, x}
    ull r; asm("mov.b64 %0, {%1, %1};" : "=l"(r) : "f"(x)); return r;
}
__device__ __forceinline__ ull pkpair(float lo, float hi) {
    ull r; asm("mov.b64 %0, {%1, %2};" : "=l"(r) : "f"(lo), "f"(hi)); return r;
}
__device__ __forceinline__ float2 upk(ull v) {
    float2 f; asm("mov.b64 {%0, %1}, %2;" : "=f"(f.x), "=f"(f.y) : "l"(v)); return f;
}
__device__ __forceinline__ float hadd2(ull v) {
    float2 f = upk(v); return f.x + f.y;
}

// ---------------- 0) fold spatial-attention kernels ----------------
__global__ void prep_k(const float* __restrict__ c1a, const float* __restrict__ c1b,
                       const float* __restrict__ c2a, const float* __restrict__ c2b,
                       const float* __restrict__ c3) {
    int tid = threadIdx.x;
    float w3 = c3[0], w7 = c3[1];
    for (int e = tid; e < 49*32; e += 256) {
        int t = e >> 5, i = e & 31;
        int ty = t / 7 - 3, tx = t % 7 - 3;
        float s = 0.f;
        for (int o = 0; o < 32; o++)
            s += c2b[o] * c2a[((o*32 + i)*7 + (tx+3))*7 + (ty+3)];
        s *= w7;
        if (tx >= -1 && tx <= 1 && ty >= -1 && ty <= 1) {
            float s1 = 0.f;
            for (int o = 0; o < 32; o++)
                s1 += c1b[o] * c1a[((o*32 + i)*3 + (tx+1))*3 + (ty+1)];
            s += w3 * s1;
        }
        g_kcomb[e] = s;
    }
}

// ---------------- 1) stats stage 1 ----------------
__global__ __launch_bounds__(256) void stats1_k(const float* __restrict__ xfu,
                                                const float* __restrict__ xhsi) {
    __shared__ float sx[256*32];
    __shared__ float sh[8][32];
    int b = blockIdx.y, blk = blockIdx.x, tid = threadIdx.x;
    size_t base = ((size_t)b*NPIX + (size_t)blk*256) * 32;
    for (int k = 0; k < 32; k++) sx[k*256 + tid] = xfu[base + (size_t)k*256 + tid];
    {
        int c = tid & 31, grp = tid >> 5;
        float s = 0.f;
        for (int p = grp; p < 256; p += 8) s += xhsi[base + (size_t)p*32 + c];
        sh[grp][c] = s;
    }
    __syncthreads();
    int e0 = tid * 4;
    int i = e0 >> 5, j0 = e0 & 31;
    float4 a = make_float4(0.f, 0.f, 0.f, 0.f);
    const float4* sx4 = (const float4*)sx;
    for (int p = 0; p < 256; p++) {
        float xi = sx[p*32 + i];
        float4 xj = sx4[p*8 + (j0 >> 2)];
        a.x += xi * xj.x; a.y += xi * xj.y; a.z += xi * xj.z; a.w += xi * xj.w;
    }
    float* part = &g_part[((size_t)b*256 + blk) * 1056];
    ((float4*)part)[tid] = a;
    if (tid < 32) {
        float t = 0.f;
        for (int g = 0; g < 8; g++) t += sh[g][tid];
        part[1024 + tid] = t;
    }
}

// ---------------- 2) stats stage 2 ----------------
__global__ __launch_bounds__(256) void stats2_k(const float* __restrict__ Wq,
                                                const float* __restrict__ Wk,
                                                const float* __restrict__ fc1,
                                                const float* __restrict__ fc2,
                                                const float* __restrict__ projW,
                                                float* __restrict__ cm_out) {
    int b = blockIdx.x, tid = threadIdx.x;
    __shared__ float scov[1024], savg[32], sQ[1024], sK[1024];
    __shared__ float snq[32], snk[32], sG[256], sA[256], shid[32];
    for (int e = tid; e < 1024; e += 256) {
        float s = 0.f;
        for (int blk = 0; blk < 256; blk++) s += g_part[((size_t)b*256 + blk)*1056 + e];
        scov[e] = s;
    }
    if (tid < 32) {
        float s = 0.f;
        for (int blk = 0; blk < 256; blk++) s += g_part[((size_t)b*256 + blk)*1056 + 1024 + tid];
        savg[tid] = s * (1.f / (float)NPIX);
    }
    __syncthreads();
    for (int e = tid; e < 2048; e += 256) {
        int which = e >> 10; int r = e & 1023; int c = r >> 5, i = r & 31;
        const float* Wm = which ? Wk : Wq;
        float s = 0.f;
        for (int j = 0; j < 32; j++) s += scov[i*32 + j] * Wm[c*32 + j];
        if (which) sK[c*32 + i] = s; else sQ[c*32 + i] = s;
    }
    __syncthreads();
    if (tid < 32) { float s = 0.f; for (int i = 0; i < 32; i++) s += Wq[tid*32+i]*sQ[tid*32+i]; snq[tid] = sqrtf(fmaxf(s, 0.f)); }
    else if (tid < 64) { int c = tid-32; float s = 0.f; for (int i = 0; i < 32; i++) s += Wk[c*32+i]*sK[c*32+i]; snk[c] = sqrtf(fmaxf(s, 0.f)); }
    {
        int h = tid >> 6, d = (tid >> 3) & 7, e = tid & 7;
        float s = 0.f;
        for (int i = 0; i < 32; i++) s += Wk[(h*8+d)*32 + i] * sQ[(h*8+e)*32 + i];
        sG[tid] = s;
    }
    if (tid >= 64 && tid < 96) {
        int o = tid - 64; float s = 0.f;
        for (int i = 0; i < 32; i++) s += fc1[o*32 + i] * savg[i];
        shid[o] = fmaxf(s, 0.f);
    }
    __syncthreads();
    if (tid < 32) {
        int h = tid >> 3, d = tid & 7;
        float l[8]; float mx = -1e30f;
        float nk = fmaxf(snk[h*8 + d], 1e-12f);
        for (int e = 0; e < 8; e++) {
            float nq = fmaxf(snq[h*8 + e], 1e-12f);
            l[e] = sG[h*64 + d*8 + e] / (nk * nq);
            mx = fmaxf(mx, l[e]);
        }
        float ssum = 0.f;
        for (int e = 0; e < 8; e++) { l[e] = expf(l[e] - mx); ssum += l[e]; }
        float inv = 1.f / ssum;
        for (int e = 0; e < 8; e++) sA[h*64 + d*8 + e] = l[e] * inv;
    } else if (tid >= 128 && tid < 160) {
        int c = tid - 128; float s = 0.f;
        for (int i = 0; i < 32; i++) s += fc2[c*32 + i] * shid[i];
        float m = sigmoidf_(s);
        cm_out[b*32 + c] = m;
        g_cmask[b*32 + c] = m;
    }
    __syncthreads();
    for (int e = tid; e < 1024; e += 256) {
        int o = e >> 5, cp = e & 31, hp = cp >> 3, dp = cp & 7;
        float s = 0.f;
        for (int d = 0; d < 8; d++) s += projW[o*32 + hp*8 + d] * sA[hp*64 + d*8 + dp];
        g_M[b*1024 + e] = s;
    }
}

// ---------------- 3) spatial mask (R3 measured-best: 16w x 32h, 4 px/thread) ----------------
#define SM_TW 16
#define SM_TH 32
#define SM_CW 22
#define SM_CWP 23
#define SM_RH 38
#define SM_STR 36
#define SMASK_XF (SM_RH*SM_CWP*SM_STR)
#define SMASK_SMEM ((SMASK_XF + 49*32) * 4)

__global__ __launch_bounds__(128) void smask_k(const float* __restrict__ xmsi,
                                               float* __restrict__ sm_out) {
    extern __shared__ float dyn[];
    float* sx = dyn;
    float* kc = dyn + SMASK_XF;
    int tid = threadIdx.x, bx = blockIdx.x, by = blockIdx.y, b = blockIdx.z;
    for (int e = tid; e < 49*32; e += 128) kc[e] = g_kcomb[e];
    for (int slot = tid; slot < SM_RH*SM_CW; slot += 128) {
        int r = slot / SM_CW, c = slot % SM_CW;
        int gh = by*SM_TH + r - 3, gw = bx*SM_TW + c - 3;
        float4* dst = (float4*)&sx[(r*SM_CWP + c)*SM_STR];
        if ((unsigned)gh < (unsigned)HH && (unsigned)gw < (unsigned)WW) {
            const float4* src = (const float4*)(xmsi + (((size_t)b*HH + gh)*WW + gw)*32);
            #pragma unroll
            for (int i4 = 0; i4 < 8; i4++) dst[i4] = src[i4];
        } else {
            #pragma unroll
            for (int i4 = 0; i4 < 8; i4++) dst[i4] = make_float4(0.f,0.f,0.f,0.f);
        }
    }
    __syncthreads();
    int ty = tid >> 2, tq = (tid & 3) * 4;
    ull acc[4];
    #pragma unroll
    for (int p = 0; p < 4; p++) acc[p] = 0ull;
    #pragma unroll 1
    for (int cg = 0; cg < 8; cg++) {
        #pragma unroll 1
        for (int dy = 0; dy < 7; dy++) {
            ulonglong2 xw[10];
            #pragma unroll
            for (int j = 0; j < 10; j++)
                xw[j] = *(const ulonglong2*)&sx[((ty+dy)*SM_CWP + tq + j)*SM_STR + cg*4];
            #pragma unroll
            for (int dx = 0; dx < 7; dx++) {
                ulonglong2 wv = *(const ulonglong2*)&kc[(dy*7 + dx)*32 + cg*4];
                #pragma unroll
                for (int p = 0; p < 4; p++) {
                    fma2(acc[p], xw[dx+p].x, wv.x);
                    fma2(acc[p], xw[dx+p].y, wv.y);
                }
            }
        }
    }
    int h = by*SM_TH + ty;
    #pragma unroll
    for (int p = 0; p < 4; p++) {
        int w = bx*SM_TW + tq + p;
        float m = sigmoidf_(hadd2(acc[p]));
        g_smask[(size_t)b*NPIX + (size_t)h*WW + w] = m;
        sm_out[(size_t)b*NPIX + (size_t)w*HH + h] = m;
    }
}

// ---------------- 4) gated V: o-pair ----------------
__global__ __launch_bounds__(256) void vgated_k(const float* __restrict__ xfu,
                                                const float* __restrict__ Wv) {
    __shared__ float ws[32*32];  // ws[i*32+o] = Wv[o*32+i]
    __shared__ float cm[32];
    int tid = threadIdx.x, h = blockIdx.x, b = blockIdx.y;
    for (int e = tid; e < 1024; e += 256) {
        int o = e >> 5, i = e & 31;
        ws[i*32 + o] = Wv[e];
    }
    if (tid < 32) cm[tid] = g_cmask[b*32 + tid];
    __syncthreads();
    size_t pidx = (size_t)b*NPIX + (size_t)h*WW + tid;
    const float4* px = (const float4*)(xfu + pidx*32);
    ull acc[16];
    #pragma unroll
    for (int q = 0; q < 16; q++) acc[q] = 0ull;
    #pragma unroll
    for (int i4 = 0; i4 < 8; i4++) {
        float4 v = px[i4];
        #pragma unroll
        for (int i = 0; i < 4; i++) {
            ull a = pk2((&v.x)[i]);
            const ulonglong2* wr = (const ulonglong2*)&ws[(i4*4 + i)*32];
            #pragma unroll
            for (int q = 0; q < 8; q++) {
                ulonglong2 wv = wr[q];
                fma2(acc[2*q], a, wv.x);
                fma2(acc[2*q+1], a, wv.y);
            }
        }
    }
    float sm = g_smask[pidx];
    float4* ob = (float4*)(g_vg + pidx*32);
    #pragma unroll
    for (int i4 = 0; i4 < 8; i4++) {
        float2 p0 = upk(acc[i4*2]), p1 = upk(acc[i4*2+1]);
        float4 r;
        r.x = p0.x * sm * cm[i4*4];
        r.y = p0.y * sm * cm[i4*4+1];
        r.z = p1.x * sm * cm[i4*4+2];
        r.w = p1.y * sm * cm[i4*4+3];
        ob[i4] = r;
    }
}

// ---------------- shared-tile loader for NHWC conv tiles ----------------
// tile: R rows x CW cols, pixel stride 36 floats (odd 16B-unit count -> conflict-free)
__device__ __forceinline__ void load_tile(float* sx, const float* __restrict__ in,
                                          int b, int h0, int w0, int R, int CW,
                                          int tid, int nthr) {
    for (int slot = tid; slot < R*CW; slot += nthr) {
        int r = slot / CW, c = slot % CW;
        int gh = h0 - 1 + r, gw = w0 - 1 + c;
        float4* dst = (float4*)&sx[slot*36];
        if ((unsigned)gh < (unsigned)HH && (unsigned)gw < (unsigned)WW) {
            const float4* src = (const float4*)(in + (((size_t)b*HH + gh)*WW + gw)*32);
            #pragma unroll
            for (int i4 = 0; i4 < 8; i4++) dst[i4] = src[i4];
        } else {
            #pragma unroll
            for (int i4 = 0; i4 < 8; i4++) dst[i4] = make_float4(0.f,0.f,0.f,0.f);
        }
    }
}

// per-pixel 3x3x32x32 accumulate from smem tile (o-pair FFMA2)
__device__ __forceinline__ void conv_accum_tile(ull (&acc)[16], const float* sx,
                                                const float* ws, int row, int col, int CW) {
    #pragma unroll 1
    for (int dh = 0; dh < 3; dh++) {
        #pragma unroll 1
        for (int dw = 0; dw < 3; dw++) {
            const float4* px = (const float4*)&sx[((row+dh)*CW + col+dw)*36];
            const float* wt = &ws[(dh*3 + dw) * 1024];
            #pragma unroll
            for (int i4 = 0; i4 < 8; i4++) {
                float4 xv = px[i4];
                #pragma unroll
                for (int i = 0; i < 4; i++) {
                    ull a = pk2((&xv.x)[i]);
                    const ulonglong2* wr = (const ulonglong2*)(wt + (i4*4 + i)*32);
                    #pragma unroll
                    for (int q = 0; q < 8; q++) {
                        ulonglong2 wv = wr[q];
                        fma2(acc[2*q],   a, wv.x);
                        fma2(acc[2*q+1], a, wv.y);
                    }
                }
            }
        }
    }
}

// ---------------- 5) tiled 3x3 conv: 2 rows x 128 px per 256-thread block ----------------
// mode 0: g_vg -> g_vspec (+x_hsi resid); mode 1: g_vspec -> g_tpos (bias+gelu)
#define CONVS_XF (4*130*36)                   // 18720 floats
#define CONVS_SMEM ((CONVS_XF + 9216 + 32)*4) // 111,872 B

__global__ __launch_bounds__(256) void conv3s_k(const float* __restrict__ wsrc,
                                                const float* __restrict__ bias,
                                                const float* __restrict__ resid,
                                                int mode, int do_gelu) {
    extern __shared__ float dyn[];
    float* sx = dyn;
    float* ws = dyn + CONVS_XF;
    float* sb = ws + 9216;
    int tid = threadIdx.x;
    for (int e = tid; e < 9216; e += 256) {
        int o = e & 31, i = (e >> 5) & 31, t = e >> 10;
        int dh = t / 3, dw = t % 3;
        ws[e] = wsrc[((o*32 + i)*3 + dw)*3 + dh];  // tap-swap for (0,3,2,1) world
    }
    if (tid < 32) sb[tid] = bias ? bias[tid] : 0.f;
    const float* in = (mode == 0) ? g_vg : g_vspec;
    float* outp = (mode == 0) ? g_vspec : g_tpos;
    int b = blockIdx.z, h0 = blockIdx.y * 2, w0 = blockIdx.x * 128;
    load_tile(sx, in, b, h0, w0, 4, 130, tid, 256);
    __syncthreads();
    int row = tid >> 7, col = tid & 127;
    ull acc[16];
    #pragma unroll
    for (int q = 0; q < 16; q++) acc[q] = pkpair(sb[2*q], sb[2*q+1]);
    conv_accum_tile(acc, sx, ws, row, col, 130);
    size_t pidx = (((size_t)b*HH + h0 + row)*WW + (w0 + col)) * 32;
    float out[32];
    #pragma unroll
    for (int q = 0; q < 16; q++) {
        float2 f = upk(acc[q]);
        out[2*q] = f.x; out[2*q+1] = f.y;
    }
    if (resid) {
        const float4* r4 = (const float4*)(resid + pidx);
        #pragma unroll
        for (int i4 = 0; i4 < 8; i4++) {
            float4 rv = r4[i4];
            out[i4*4] += rv.x; out[i4*4+1] += rv.y; out[i4*4+2] += rv.z; out[i4*4+3] += rv.w;
        }
    }
    if (do_gelu) {
        #pragma unroll
        for (int o = 0; o < 32; o++) out[o] = gelu_exact(out[o]);
    }
    float4* ob = (float4*)(outp + pidx);
    #pragma unroll
    for (int i4 = 0; i4 < 8; i4++)
        ob[i4] = make_float4(out[i4*4], out[i4*4+1], out[i4*4+2], out[i4*4+3]);
}

// ---------------- 6) final: tiled conv(t_pos) + fused matvec/gelu epilogue ----------------
// 2 rows x 64 px per 128-thread block
#define FIN_XF (4*66*36)                       // 9504 floats
#define FIN_SMEM ((FIN_XF + 9216 + 1024 + 64)*4)  // 79,232 B

__global__ __launch_bounds__(128) void final_s_k(const float* __restrict__ w2src,
                                                 const float* __restrict__ b2,
                                                 const float* __restrict__ projb) {
    extern __shared__ float dyn[];
    float* sx = dyn;
    float* ws = dyn + FIN_XF;
    float* wm = ws + 9216;        // wm[c*32+o] = M[o][c]
    float* sb2 = wm + 1024;
    float* spb = sb2 + 32;
    int tid = threadIdx.x;
    int b = blockIdx.z, h0 = blockIdx.y * 2, w0 = blockIdx.x * 64;
    for (int e = tid; e < 9216; e += 128) {
        int o = e & 31, i = (e >> 5) & 31, t = e >> 10;
        int dh = t / 3, dw = t % 3;
        ws[e] = w2src[((o*32 + i)*3 + dw)*3 + dh];
    }
    for (int e = tid; e < 1024; e += 128) {
        int c = e >> 5, o = e & 31;
        wm[c*32 + o] = g_M[b*1024 + o*32 + c];
    }
    if (tid < 32) { sb2[tid] = b2[tid]; spb[tid] = projb[tid]; }
    load_tile(sx, g_tpos, b, h0, w0, 4, 66, tid, 128);
    __syncthreads();
    int row = tid >> 6, col = tid & 63;
    ull acc[16];
    #pragma unroll
    for (int q = 0; q < 16; q++) acc[q] = pkpair(sb2[2*q], sb2[2*q+1]);
    conv_accum_tile(acc, sx, ws, row, col, 66);
    size_t pidx = (((size_t)b*HH + h0 + row)*WW + (w0 + col)) * 32;
    // matvec M @ v_spec
    ull mv[16];
    #pragma unroll
    for (int q = 0; q < 16; q++) mv[q] = pkpair(spb[2*q], spb[2*q+1]);
    {
        const float4* pv = (const float4*)(g_vspec + pidx);
        #pragma unroll
        for (int i4 = 0; i4 < 8; i4++) {
            float4 v = pv[i4];
            #pragma unroll
            for (int i = 0; i < 4; i++) {
                ull a = pk2((&v.x)[i]);
                const ulonglong2* wr = (const ulonglong2*)&wm[(i4*4 + i)*32];
                #pragma unroll
                for (int q = 0; q < 8; q++) {
                    ulonglong2 wv = wr[q];
                    fma2(mv[2*q],   a, wv.x);
                    fma2(mv[2*q+1], a, wv.y);
                }
            }
        }
    }
    float4* ob = (float4*)(g_outn + pidx);
    #pragma unroll
    for (int q4 = 0; q4 < 8; q4++) {
        float2 c0 = upk(acc[2*q4]), c1 = upk(acc[2*q4+1]);
        float2 m0 = upk(mv[2*q4]),  m1 = upk(mv[2*q4+1]);
        float4 r;
        r.x = gelu_exact(m0.x) + c0.x;
        r.y = gelu_exact(m0.y) + c0.y;
        r.z = gelu_exact(m1.x) + c1.x;
        r.w = gelu_exact(m1.y) + c1.y;
        ob[q4] = r;
    }
}

// ---------------- 7) transpose NHWC -> (b,c,w,h) ----------------
__global__ void transpose_k(float* __restrict__ out0) {
    __shared__ float tile[32][33];
    int b = blockIdx.z, w = blockIdx.y, h0 = blockIdx.x * 32;
    int tx = threadIdx.x, ty = threadIdx.y;
    tile[ty][tx] = g_outn[(((size_t)b*HH + (h0 + ty))*WW + w)*32 + tx];
    __syncthreads();
    out0[(((size_t)b*CC + ty)*WW + w)*HH + h0 + tx] = tile[tx][ty];
}

// ---------------- launch ----------------
extern "C" void kernel_launch(void* const* d_in, const int* in_sizes, int n_in,
                              void* d_out, int out_size) {
    const float* x_fu   = (const float*)d_in[0];
    const float* x_msi  = (const float*)d_in[1];
    const float* x_hsi  = (const float*)d_in[2];
    const float* Wq     = (const float*)d_in[3];
    const float* Wk     = (const float*)d_in[4];
    const float* Wv     = (const float*)d_in[5];
    const float* proj_W = (const float*)d_in[6];
    const float* proj_b = (const float*)d_in[7];
    const float* pos1_W = (const float*)d_in[8];
    const float* pos1_b = (const float*)d_in[9];
    const float* pos2_W = (const float*)d_in[10];
    const float* pos2_b = (const float*)d_in[11];
    const float* ca_fc1 = (const float*)d_in[12];
    const float* ca_fc2 = (const float*)d_in[13];
    const float* sa_c1a = (const float*)d_in[14];
    const float* sa_c1b = (const float*)d_in[15];
    const float* sa_c2a = (const float*)d_in[16];
    const float* sa_c2b = (const float*)d_in[17];
    const float* sa_c3  = (const float*)d_in[18];
    const float* attn_W = (const float*)d_in[19];

    float* out0   = (float*)d_out;
    float* cm_out = out0 + IMG_ELEMS;
    float* sm_out = cm_out + BB*CC;

    cudaFuncSetAttribute(smask_k,  cudaFuncAttributeMaxDynamicSharedMemorySize, SMASK_SMEM);
    cudaFuncSetAttribute(conv3s_k, cudaFuncAttributeMaxDynamicSharedMemorySize, CONVS_SMEM);
    cudaFuncSetAttribute(final_s_k, cudaFuncAttributeMaxDynamicSharedMemorySize, FIN_SMEM);

    prep_k  <<<1, 256>>>(sa_c1a, sa_c1b, sa_c2a, sa_c2b, sa_c3);
    stats1_k<<<dim3(256, BB), 256>>>(x_fu, x_hsi);
    stats2_k<<<BB, 256>>>(Wq, Wk, ca_fc1, ca_fc2, proj_W, cm_out);
    smask_k <<<dim3(WW/SM_TW, HH/SM_TH, BB), 128, SMASK_SMEM>>>(x_msi, sm_out);
    vgated_k<<<dim3(HH, BB), 256>>>(x_fu, Wv);
    dim3 cg(WW/128, HH/2, BB);
    conv3s_k<<<cg, 256, CONVS_SMEM>>>(attn_W, (const float*)nullptr, x_hsi, 0, 0);   // v_spec
    conv3s_k<<<cg, 256, CONVS_SMEM>>>(pos1_W, pos1_b, (const float*)nullptr, 1, 1);  // t_pos
    final_s_k<<<dim3(WW/64, HH/2, BB), 128, FIN_SMEM>>>(pos2_W, pos2_b, proj_b);
    transpose_k<<<dim3(HH/32, WW, BB), dim3(32, 32)>>>(out0);
}

// round 10
// speedup vs baseline: 1.1974x; 1.1974x over previous
#include <cuda_runtime.h>
#include <math.h>

// ---------------- problem constants ----------------
#define BB 4
#define HH 256
#define WW 256
#define CC 32
#define NPIX (HH*WW)            // 65536
#define IMG_ELEMS (BB*NPIX*CC)  // 8388608

typedef unsigned long long ull;

// ---------------- device scratch ----------------
__device__ float g_part[BB*256*1056];
__device__ float g_M[BB*1024];
__device__ float g_cmask[BB*CC];
__device__ float g_smask[BB*NPIX];
__device__ float g_kcomb[49*32];
__device__ float g_vg[IMG_ELEMS];
__device__ float g_vspec[IMG_ELEMS];
__device__ float g_tpos[IMG_ELEMS];
__device__ float g_outn[IMG_ELEMS];

__device__ __forceinline__ float gelu_exact(float x) {
    return 0.5f * x * (1.0f + erff(x * 0.70710678118654752f));
}
__device__ __forceinline__ float sigmoidf_(float x) {
    return 1.0f / (1.0f + expf(-x));
}

// ---------------- packed f32x2 helpers ----------------
__device__ __forceinline__ void fma2(ull& c, ull a, ull b) {
    asm("fma.rn.f32x2 %0, %1, %2, %0;" : "+l"(c) : "l"(a), "l"(b));
}
__device__ __forceinline__ ull pk2(float x) {          // {x, x}
    ull r; asm("mov.b64 %0, {%1, %1};" : "=l"(r) : "f"(x)); return r;
}
__device__ __forceinline__ ull pkpair(float lo, float hi) {
    ull r; asm("mov.b64 %0, {%1, %2};" : "=l"(r) : "f"(lo), "f"(hi)); return r;
}
__device__ __forceinline__ float2 upk(ull v) {
    float2 f; asm("mov.b64 {%0, %1}, %2;" : "=f"(f.x), "=f"(f.y) : "l"(v)); return f;
}
__device__ __forceinline__ float hadd2(ull v) {
    float2 f = upk(v); return f.x + f.y;
}

// ---------------- 0) fold spatial-attention kernels ----------------
__global__ void prep_k(const float* __restrict__ c1a, const float* __restrict__ c1b,
                       const float* __restrict__ c2a, const float* __restrict__ c2b,
                       const float* __restrict__ c3) {
    int tid = threadIdx.x;
    float w3 = c3[0], w7 = c3[1];
    for (int e = tid; e < 49*32; e += 256) {
        int t = e >> 5, i = e & 31;
        int ty = t / 7 - 3, tx = t % 7 - 3;
        float s = 0.f;
        for (int o = 0; o < 32; o++)
            s += c2b[o] * c2a[((o*32 + i)*7 + (tx+3))*7 + (ty+3)];
        s *= w7;
        if (tx >= -1 && tx <= 1 && ty >= -1 && ty <= 1) {
            float s1 = 0.f;
            for (int o = 0; o < 32; o++)
                s1 += c1b[o] * c1a[((o*32 + i)*3 + (tx+1))*3 + (ty+1)];
            s += w3 * s1;
        }
        g_kcomb[e] = s;
    }
}

// ---------------- 1) stats stage 1 ----------------
__global__ __launch_bounds__(256) void stats1_k(const float* __restrict__ xfu,
                                                const float* __restrict__ xhsi) {
    __shared__ float sx[256*32];
    __shared__ float sh[8][32];
    int b = blockIdx.y, blk = blockIdx.x, tid = threadIdx.x;
    size_t base = ((size_t)b*NPIX + (size_t)blk*256) * 32;
    for (int k = 0; k < 32; k++) sx[k*256 + tid] = xfu[base + (size_t)k*256 + tid];
    {
        int c = tid & 31, grp = tid >> 5;
        float s = 0.f;
        for (int p = grp; p < 256; p += 8) s += xhsi[base + (size_t)p*32 + c];
        sh[grp][c] = s;
    }
    __syncthreads();
    int e0 = tid * 4;
    int i = e0 >> 5, j0 = e0 & 31;
    float4 a = make_float4(0.f, 0.f, 0.f, 0.f);
    const float4* sx4 = (const float4*)sx;
    for (int p = 0; p < 256; p++) {
        float xi = sx[p*32 + i];
        float4 xj = sx4[p*8 + (j0 >> 2)];
        a.x += xi * xj.x; a.y += xi * xj.y; a.z += xi * xj.z; a.w += xi * xj.w;
    }
    float* part = &g_part[((size_t)b*256 + blk) * 1056];
    ((float4*)part)[tid] = a;
    if (tid < 32) {
        float t = 0.f;
        for (int g = 0; g < 8; g++) t += sh[g][tid];
        part[1024 + tid] = t;
    }
}

// ---------------- 2) stats stage 2 ----------------
__global__ __launch_bounds__(256) void stats2_k(const float* __restrict__ Wq,
                                                const float* __restrict__ Wk,
                                                const float* __restrict__ fc1,
                                                const float* __restrict__ fc2,
                                                const float* __restrict__ projW,
                                                float* __restrict__ cm_out) {
    int b = blockIdx.x, tid = threadIdx.x;
    __shared__ float scov[1024], savg[32], sQ[1024], sK[1024];
    __shared__ float snq[32], snk[32], sG[256], sA[256], shid[32];
    for (int e = tid; e < 1024; e += 256) {
        float s = 0.f;
        for (int blk = 0; blk < 256; blk++) s += g_part[((size_t)b*256 + blk)*1056 + e];
        scov[e] = s;
    }
    if (tid < 32) {
        float s = 0.f;
        for (int blk = 0; blk < 256; blk++) s += g_part[((size_t)b*256 + blk)*1056 + 1024 + tid];
        savg[tid] = s * (1.f / (float)NPIX);
    }
    __syncthreads();
    for (int e = tid; e < 2048; e += 256) {
        int which = e >> 10; int r = e & 1023; int c = r >> 5, i = r & 31;
        const float* Wm = which ? Wk : Wq;
        float s = 0.f;
        for (int j = 0; j < 32; j++) s += scov[i*32 + j] * Wm[c*32 + j];
        if (which) sK[c*32 + i] = s; else sQ[c*32 + i] = s;
    }
    __syncthreads();
    if (tid < 32) { float s = 0.f; for (int i = 0; i < 32; i++) s += Wq[tid*32+i]*sQ[tid*32+i]; snq[tid] = sqrtf(fmaxf(s, 0.f)); }
    else if (tid < 64) { int c = tid-32; float s = 0.f; for (int i = 0; i < 32; i++) s += Wk[c*32+i]*sK[c*32+i]; snk[c] = sqrtf(fmaxf(s, 0.f)); }
    {
        int h = tid >> 6, d = (tid >> 3) & 7, e = tid & 7;
        float s = 0.f;
        for (int i = 0; i < 32; i++) s += Wk[(h*8+d)*32 + i] * sQ[(h*8+e)*32 + i];
        sG[tid] = s;
    }
    if (tid >= 64 && tid < 96) {
        int o = tid - 64; float s = 0.f;
        for (int i = 0; i < 32; i++) s += fc1[o*32 + i] * savg[i];
        shid[o] = fmaxf(s, 0.f);
    }
    __syncthreads();
    if (tid < 32) {
        int h = tid >> 3, d = tid & 7;
        float l[8]; float mx = -1e30f;
        float nk = fmaxf(snk[h*8 + d], 1e-12f);
        for (int e = 0; e < 8; e++) {
            float nq = fmaxf(snq[h*8 + e], 1e-12f);
            l[e] = sG[h*64 + d*8 + e] / (nk * nq);
            mx = fmaxf(mx, l[e]);
        }
        float ssum = 0.f;
        for (int e = 0; e < 8; e++) { l[e] = expf(l[e] - mx); ssum += l[e]; }
        float inv = 1.f / ssum;
        for (int e = 0; e < 8; e++) sA[h*64 + d*8 + e] = l[e] * inv;
    } else if (tid >= 128 && tid < 160) {
        int c = tid - 128; float s = 0.f;
        for (int i = 0; i < 32; i++) s += fc2[c*32 + i] * shid[i];
        float m = sigmoidf_(s);
        cm_out[b*32 + c] = m;
        g_cmask[b*32 + c] = m;
    }
    __syncthreads();
    for (int e = tid; e < 1024; e += 256) {
        int o = e >> 5, cp = e & 31, hp = cp >> 3, dp = cp & 7;
        float s = 0.f;
        for (int d = 0; d < 8; d++) s += projW[o*32 + hp*8 + d] * sA[hp*64 + d*8 + dp];
        g_M[b*1024 + e] = s;
    }
}

// ---------------- 3) spatial mask (R3 measured-best: 16w x 32h, 4 px/thread) ----------------
#define SM_TW 16
#define SM_TH 32
#define SM_CW 22
#define SM_CWP 23
#define SM_RH 38
#define SM_STR 36
#define SMASK_XF (SM_RH*SM_CWP*SM_STR)
#define SMASK_SMEM ((SMASK_XF + 49*32) * 4)

__global__ __launch_bounds__(128) void smask_k(const float* __restrict__ xmsi,
                                               float* __restrict__ sm_out) {
    extern __shared__ float dyn[];
    float* sx = dyn;
    float* kc = dyn + SMASK_XF;
    int tid = threadIdx.x, bx = blockIdx.x, by = blockIdx.y, b = blockIdx.z;
    for (int e = tid; e < 49*32; e += 128) kc[e] = g_kcomb[e];
    for (int slot = tid; slot < SM_RH*SM_CW; slot += 128) {
        int r = slot / SM_CW, c = slot % SM_CW;
        int gh = by*SM_TH + r - 3, gw = bx*SM_TW + c - 3;
        float4* dst = (float4*)&sx[(r*SM_CWP + c)*SM_STR];
        if ((unsigned)gh < (unsigned)HH && (unsigned)gw < (unsigned)WW) {
            const float4* src = (const float4*)(xmsi + (((size_t)b*HH + gh)*WW + gw)*32);
            #pragma unroll
            for (int i4 = 0; i4 < 8; i4++) dst[i4] = src[i4];
        } else {
            #pragma unroll
            for (int i4 = 0; i4 < 8; i4++) dst[i4] = make_float4(0.f,0.f,0.f,0.f);
        }
    }
    __syncthreads();
    int ty = tid >> 2, tq = (tid & 3) * 4;
    ull acc[4];
    #pragma unroll
    for (int p = 0; p < 4; p++) acc[p] = 0ull;
    #pragma unroll 1
    for (int cg = 0; cg < 8; cg++) {
        #pragma unroll 1
        for (int dy = 0; dy < 7; dy++) {
            ulonglong2 xw[10];
            #pragma unroll
            for (int j = 0; j < 10; j++)
                xw[j] = *(const ulonglong2*)&sx[((ty+dy)*SM_CWP + tq + j)*SM_STR + cg*4];
            #pragma unroll
            for (int dx = 0; dx < 7; dx++) {
                ulonglong2 wv = *(const ulonglong2*)&kc[(dy*7 + dx)*32 + cg*4];
                #pragma unroll
                for (int p = 0; p < 4; p++) {
                    fma2(acc[p], xw[dx+p].x, wv.x);
                    fma2(acc[p], xw[dx+p].y, wv.y);
                }
            }
        }
    }
    int h = by*SM_TH + ty;
    #pragma unroll
    for (int p = 0; p < 4; p++) {
        int w = bx*SM_TW + tq + p;
        float m = sigmoidf_(hadd2(acc[p]));
        g_smask[(size_t)b*NPIX + (size_t)h*WW + w] = m;
        sm_out[(size_t)b*NPIX + (size_t)w*HH + h] = m;
    }
}

// ---------------- 4) gated V: o-pair ----------------
__global__ __launch_bounds__(256) void vgated_k(const float* __restrict__ xfu,
                                                const float* __restrict__ Wv) {
    __shared__ float ws[32*32];  // ws[i*32+o] = Wv[o*32+i]
    __shared__ float cm[32];
    int tid = threadIdx.x, h = blockIdx.x, b = blockIdx.y;
    for (int e = tid; e < 1024; e += 256) {
        int o = e >> 5, i = e & 31;
        ws[i*32 + o] = Wv[e];
    }
    if (tid < 32) cm[tid] = g_cmask[b*32 + tid];
    __syncthreads();
    size_t pidx = (size_t)b*NPIX + (size_t)h*WW + tid;
    const float4* px = (const float4*)(xfu + pidx*32);
    ull acc[16];
    #pragma unroll
    for (int q = 0; q < 16; q++) acc[q] = 0ull;
    #pragma unroll
    for (int i4 = 0; i4 < 8; i4++) {
        float4 v = px[i4];
        #pragma unroll
        for (int i = 0; i < 4; i++) {
            ull a = pk2((&v.x)[i]);
            const ulonglong2* wr = (const ulonglong2*)&ws[(i4*4 + i)*32];
            #pragma unroll
            for (int q = 0; q < 8; q++) {
                ulonglong2 wv = wr[q];
                fma2(acc[2*q], a, wv.x);
                fma2(acc[2*q+1], a, wv.y);
            }
        }
    }
    float sm = g_smask[pidx];
    float4* ob = (float4*)(g_vg + pidx*32);
    #pragma unroll
    for (int i4 = 0; i4 < 8; i4++) {
        float2 p0 = upk(acc[i4*2]), p1 = upk(acc[i4*2+1]);
        float4 r;
        r.x = p0.x * sm * cm[i4*4];
        r.y = p0.y * sm * cm[i4*4+1];
        r.z = p1.x * sm * cm[i4*4+2];
        r.w = p1.y * sm * cm[i4*4+3];
        ob[i4] = r;
    }
}

// ---------------- common: coalesced + conflict-free tile loader ----------------
// tile: 4 rows x 258 cols, pixel stride 36 floats; flat float4 mapping
#define CT_CW 258
#define CT_TR 4
#define CT_XF (CT_TR*CT_CW*36)            // 37152 floats
__device__ __forceinline__ void load_tile4(float* sx, const float* __restrict__ in,
                                           int b, int h0, int tid) {
    for (int f = tid; f < CT_TR*CT_CW*8; f += 128) {
        int px = f >> 3, i4 = f & 7;
        int r = px / CT_CW, c = px - r*CT_CW;
        int gh = h0 - 1 + r, gw = c - 1;
        float4 v = make_float4(0.f, 0.f, 0.f, 0.f);
        if ((unsigned)gh < (unsigned)HH && (unsigned)gw < (unsigned)WW)
            v = ((const float4*)(in + (((size_t)b*HH + gh)*WW + gw)*32))[i4];
        *(float4*)&sx[px*36 + i4*4] = v;
    }
}

// conv accumulation over one output half (16 ch), 4 px/thread, weights chunked in regs
__device__ __forceinline__ void conv_half(ull (&acc)[4][8], const float* sx,
                                          const float* ws, int row, int base, int oh) {
    #pragma unroll 1
    for (int dh = 0; dh < 3; dh++) {
        const float* xrow = &sx[(row + dh)*CT_CW*36];
        #pragma unroll 1
        for (int i4 = 0; i4 < 8; i4++) {
            float4 xv[4][3];
            #pragma unroll
            for (int k = 0; k < 4; k++)
                #pragma unroll
                for (int dw = 0; dw < 3; dw++)
                    xv[k][dw] = *(const float4*)&xrow[(base + k*32 + dw)*36 + i4*4];
            #pragma unroll
            for (int i = 0; i < 4; i++) {
                ull a[4][3];
                #pragma unroll
                for (int k = 0; k < 4; k++)
                    #pragma unroll
                    for (int dw = 0; dw < 3; dw++)
                        a[k][dw] = pk2((&xv[k][dw].x)[i]);
                #pragma unroll
                for (int dw = 0; dw < 3; dw++) {
                    const ulonglong2* wp = (const ulonglong2*)&ws[(dh*3 + dw)*1024 + (i4*4 + i)*32 + oh*16];
                    ulonglong2 wA = wp[0], wB = wp[1];
                    #pragma unroll
                    for (int k = 0; k < 4; k++) {
                        fma2(acc[k][0], a[k][dw], wA.x);
                        fma2(acc[k][1], a[k][dw], wA.y);
                        fma2(acc[k][2], a[k][dw], wB.x);
                        fma2(acc[k][3], a[k][dw], wB.y);
                    }
                    ulonglong2 wC = wp[2], wD = wp[3];
                    #pragma unroll
                    for (int k = 0; k < 4; k++) {
                        fma2(acc[k][4], a[k][dw], wC.x);
                        fma2(acc[k][5], a[k][dw], wC.y);
                        fma2(acc[k][6], a[k][dw], wD.x);
                        fma2(acc[k][7], a[k][dw], wD.y);
                    }
                }
            }
        }
    }
}

// ---------------- 5) conv3: 2 rows x 256 px per 128-thread block, 4 px/thread ----------------
#define CONVS_SMEM ((CT_XF + 9216 + 32)*4)   // 185,600 B
__global__ __launch_bounds__(128) void conv3s_k(const float* __restrict__ wsrc,
                                                const float* __restrict__ bias,
                                                const float* __restrict__ resid,
                                                int mode, int do_gelu) {
    extern __shared__ float dyn[];
    float* sx = dyn;
    float* ws = dyn + CT_XF;
    float* sb = ws + 9216;
    int tid = threadIdx.x, b = blockIdx.y, h0 = blockIdx.x * 2;
    for (int e = tid; e < 9216; e += 128) {
        int o = e & 31, i = (e >> 5) & 31, t = e >> 10;
        int dh = t / 3, dw = t % 3;
        ws[e] = wsrc[((o*32 + i)*3 + dw)*3 + dh];  // tap-swap for (0,3,2,1) world
    }
    if (tid < 32) sb[tid] = bias ? bias[tid] : 0.f;
    const float* in = (mode == 0) ? g_vg : g_vspec;
    float* outp = (mode == 0) ? g_vspec : g_tpos;
    load_tile4(sx, in, b, h0, tid);
    __syncthreads();
    int row = tid >> 6;
    int base = ((tid >> 5) & 1) * 128 + (tid & 31);
    #pragma unroll 1
    for (int oh = 0; oh < 2; oh++) {
        ull acc[4][8];
        #pragma unroll
        for (int k = 0; k < 4; k++)
            #pragma unroll
            for (int q = 0; q < 8; q++)
                acc[k][q] = pkpair(sb[oh*16 + 2*q], sb[oh*16 + 2*q + 1]);
        conv_half(acc, sx, ws, row, base, oh);
        #pragma unroll
        for (int k = 0; k < 4; k++) {
            size_t pidx = (((size_t)b*HH + h0 + row)*WW + (base + k*32)) * 32 + oh*16;
            float out[16];
            #pragma unroll
            for (int q = 0; q < 8; q++) {
                float2 f2 = upk(acc[k][q]);
                out[2*q] = f2.x; out[2*q+1] = f2.y;
            }
            if (resid) {
                const float4* r4 = (const float4*)(resid + pidx);
                #pragma unroll
                for (int j = 0; j < 4; j++) {
                    float4 rv = r4[j];
                    out[j*4] += rv.x; out[j*4+1] += rv.y; out[j*4+2] += rv.z; out[j*4+3] += rv.w;
                }
            }
            if (do_gelu) {
                #pragma unroll
                for (int o = 0; o < 16; o++) out[o] = gelu_exact(out[o]);
            }
            float4* ob = (float4*)(outp + pidx);
            #pragma unroll
            for (int j = 0; j < 4; j++)
                ob[j] = make_float4(out[j*4], out[j*4+1], out[j*4+2], out[j*4+3]);
        }
    }
}

// ---------------- 6) final: conv(t_pos) + matvec(M @ v_spec) fused ----------------
#define FIN_SMEM ((CT_XF + 9216 + 1024 + 64)*4)   // 189,824 B
__global__ __launch_bounds__(128) void final_s_k(const float* __restrict__ w2src,
                                                 const float* __restrict__ b2,
                                                 const float* __restrict__ projb) {
    extern __shared__ float dyn[];
    float* sx = dyn;
    float* ws = dyn + CT_XF;
    float* wm = ws + 9216;        // wm[c*32+o] = M[o][c]
    float* sb2 = wm + 1024;
    float* spb = sb2 + 32;
    int tid = threadIdx.x, b = blockIdx.y, h0 = blockIdx.x * 2;
    for (int e = tid; e < 9216; e += 128) {
        int o = e & 31, i = (e >> 5) & 31, t = e >> 10;
        int dh = t / 3, dw = t % 3;
        ws[e] = w2src[((o*32 + i)*3 + dw)*3 + dh];
    }
    for (int e = tid; e < 1024; e += 128) {
        int c = e >> 5, o = e & 31;
        wm[c*32 + o] = g_M[b*1024 + o*32 + c];
    }
    if (tid < 32) { sb2[tid] = b2[tid]; spb[tid] = projb[tid]; }
    load_tile4(sx, g_tpos, b, h0, tid);
    __syncthreads();
    int row = tid >> 6;
    int base = ((tid >> 5) & 1) * 128 + (tid & 31);
    #pragma unroll 1
    for (int oh = 0; oh < 2; oh++) {
        ull acc[4][8];
        #pragma unroll
        for (int k = 0; k < 4; k++)
            #pragma unroll
            for (int q = 0; q < 8; q++)
                acc[k][q] = pkpair(sb2[oh*16 + 2*q], sb2[oh*16 + 2*q + 1]);
        conv_half(acc, sx, ws, row, base, oh);
        // matvec M @ v_spec for the 4 pixels, same output half, weights chunked
        ull mv[4][8];
        #pragma unroll
        for (int k = 0; k < 4; k++)
            #pragma unroll
            for (int q = 0; q < 8; q++)
                mv[k][q] = pkpair(spb[oh*16 + 2*q], spb[oh*16 + 2*q + 1]);
        size_t prow = ((size_t)b*HH + h0 + row)*WW;
        #pragma unroll 1
        for (int i4 = 0; i4 < 8; i4++) {
            float4 v[4];
            #pragma unroll
            for (int k = 0; k < 4; k++)
                v[k] = ((const float4*)(g_vspec + (prow + base + k*32)*32))[i4];
            #pragma unroll
            for (int i = 0; i < 4; i++) {
                ull a[4];
                #pragma unroll
                for (int k = 0; k < 4; k++) a[k] = pk2((&v[k].x)[i]);
                const ulonglong2* wp = (const ulonglong2*)&wm[(i4*4 + i)*32 + oh*16];
                ulonglong2 wA = wp[0], wB = wp[1];
                #pragma unroll
                for (int k = 0; k < 4; k++) {
                    fma2(mv[k][0], a[k], wA.x);
                    fma2(mv[k][1], a[k], wA.y);
                    fma2(mv[k][2], a[k], wB.x);
                    fma2(mv[k][3], a[k], wB.y);
                }
                ulonglong2 wC = wp[2], wD = wp[3];
                #pragma unroll
                for (int k = 0; k < 4; k++) {
                    fma2(mv[k][4], a[k], wC.x);
                    fma2(mv[k][5], a[k], wC.y);
                    fma2(mv[k][6], a[k], wD.x);
                    fma2(mv[k][7], a[k], wD.y);
                }
            }
        }
        #pragma unroll
        for (int k = 0; k < 4; k++) {
            size_t pidx = (prow + base + k*32) * 32 + oh*16;
            float4* ob = (float4*)(g_outn + pidx);
            #pragma unroll
            for (int j = 0; j < 2; j++) {
                float2 c0 = upk(acc[k][j*4]),   c1 = upk(acc[k][j*4+1]);
                float2 c2 = upk(acc[k][j*4+2]), c3 = upk(acc[k][j*4+3]);
                float2 m0 = upk(mv[k][j*4]),    m1 = upk(mv[k][j*4+1]);
                float2 m2 = upk(mv[k][j*4+2]),  m3 = upk(mv[k][j*4+3]);
                ob[j*2]   = make_float4(gelu_exact(m0.x) + c0.x, gelu_exact(m0.y) + c0.y,
                                        gelu_exact(m1.x) + c1.x, gelu_exact(m1.y) + c1.y);
                ob[j*2+1] = make_float4(gelu_exact(m2.x) + c2.x, gelu_exact(m2.y) + c2.y,
                                        gelu_exact(m3.x) + c3.x, gelu_exact(m3.y) + c3.y);
            }
        }
    }
}

// ---------------- 7) transpose NHWC -> (b,c,w,h) ----------------
__global__ void transpose_k(float* __restrict__ out0) {
    __shared__ float tile[32][33];
    int b = blockIdx.z, w = blockIdx.y, h0 = blockIdx.x * 32;
    int tx = threadIdx.x, ty = threadIdx.y;
    tile[ty][tx] = g_outn[(((size_t)b*HH + (h0 + ty))*WW + w)*32 + tx];
    __syncthreads();
    out0[(((size_t)b*CC + ty)*WW + w)*HH + h0 + tx] = tile[tx][ty];
}

// ---------------- launch ----------------
extern "C" void kernel_launch(void* const* d_in, const int* in_sizes, int n_in,
                              void* d_out, int out_size) {
    const float* x_fu   = (const float*)d_in[0];
    const float* x_msi  = (const float*)d_in[1];
    const float* x_hsi  = (const float*)d_in[2];
    const float* Wq     = (const float*)d_in[3];
    const float* Wk     = (const float*)d_in[4];
    const float* Wv     = (const float*)d_in[5];
    const float* proj_W = (const float*)d_in[6];
    const float* proj_b = (const float*)d_in[7];
    const float* pos1_W = (const float*)d_in[8];
    const float* pos1_b = (const float*)d_in[9];
    const float* pos2_W = (const float*)d_in[10];
    const float* pos2_b = (const float*)d_in[11];
    const float* ca_fc1 = (const float*)d_in[12];
    const float* ca_fc2 = (const float*)d_in[13];
    const float* sa_c1a = (const float*)d_in[14];
    const float* sa_c1b = (const float*)d_in[15];
    const float* sa_c2a = (const float*)d_in[16];
    const float* sa_c2b = (const float*)d_in[17];
    const float* sa_c3  = (const float*)d_in[18];
    const float* attn_W = (const float*)d_in[19];

    float* out0   = (float*)d_out;
    float* cm_out = out0 + IMG_ELEMS;
    float* sm_out = cm_out + BB*CC;

    cudaFuncSetAttribute(smask_k,   cudaFuncAttributeMaxDynamicSharedMemorySize, SMASK_SMEM);
    cudaFuncSetAttribute(conv3s_k,  cudaFuncAttributeMaxDynamicSharedMemorySize, CONVS_SMEM);
    cudaFuncSetAttribute(final_s_k, cudaFuncAttributeMaxDynamicSharedMemorySize, FIN_SMEM);

    prep_k  <<<1, 256>>>(sa_c1a, sa_c1b, sa_c2a, sa_c2b, sa_c3);
    stats1_k<<<dim3(256, BB), 256>>>(x_fu, x_hsi);
    stats2_k<<<BB, 256>>>(Wq, Wk, ca_fc1, ca_fc2, proj_W, cm_out);
    smask_k <<<dim3(WW/SM_TW, HH/SM_TH, BB), 128, SMASK_SMEM>>>(x_msi, sm_out);
    vgated_k<<<dim3(HH, BB), 256>>>(x_fu, Wv);
    dim3 cg(HH/2, BB);
    conv3s_k<<<cg, 128, CONVS_SMEM>>>(attn_W, (const float*)nullptr, x_hsi, 0, 0);   // v_spec
    conv3s_k<<<cg, 128, CONVS_SMEM>>>(pos1_W, pos1_b, (const float*)nullptr, 1, 1);  // t_pos
    final_s_k<<<cg, 128, FIN_SMEM>>>(pos2_W, pos2_b, proj_b);
    transpose_k<<<dim3(HH/32, WW, BB), dim3(32, 32)>>>(out0);
}

// round 12
// speedup vs baseline: 1.4148x; 1.1815x over previous
#include <cuda_runtime.h>
#include <cuda_bf16.h>
#include <stdint.h>
#include <math.h>

// ---------------- problem constants ----------------
#define BB 4
#define HH 256
#define WW 256
#define CC 32
#define NPIX (HH*WW)            // 65536
#define IMG_ELEMS (BB*NPIX*CC)  // 8388608

typedef unsigned long long ull;

// ---------------- device scratch ----------------
__device__ float g_part[BB*256*1056];
__device__ float g_M[BB*1024];
__device__ float g_cmask[BB*CC];
__device__ float g_smask[BB*NPIX];
__device__ float g_kcomb[49*32];
__device__ float g_vspec[IMG_ELEMS];
__device__ float g_tpos[IMG_ELEMS];
__device__ float g_outn[IMG_ELEMS];
__device__ __nv_bfloat16 g_vg_hi[IMG_ELEMS], g_vg_lo[IMG_ELEMS];
__device__ __nv_bfloat16 g_vs_hi[IMG_ELEMS], g_vs_lo[IMG_ELEMS];
// padded bf16 weight tiles for mma convs: [conv 2][pass 2][dh 3][o 32][k 104]
#define WB_ROWS (6*32)
#define WB_STR  104
__device__ __nv_bfloat16 g_Wb[2*WB_ROWS*WB_STR];

__device__ __forceinline__ float gelu_exact(float x) {
    return 0.5f * x * (1.0f + erff(x * 0.70710678118654752f));
}
__device__ __forceinline__ float sigmoidf_(float x) {
    return 1.0f / (1.0f + expf(-x));
}

// ---------------- packed f32x2 helpers ----------------
__device__ __forceinline__ void fma2(ull& c, ull a, ull b) {
    asm("fma.rn.f32x2 %0, %1, %2, %0;" : "+l"(c) : "l"(a), "l"(b));
}
__device__ __forceinline__ ull pk2(float x) {
    ull r; asm("mov.b64 %0, {%1, %1};" : "=l"(r) : "f"(x)); return r;
}
__device__ __forceinline__ ull pkpair(float lo, float hi) {
    ull r; asm("mov.b64 %0, {%1, %2};" : "=l"(r) : "f"(lo), "f"(hi)); return r;
}
__device__ __forceinline__ float2 upk(ull v) {
    float2 f; asm("mov.b64 {%0, %1}, %2;" : "=f"(f.x), "=f"(f.y) : "l"(v)); return f;
}
__device__ __forceinline__ float hadd2(ull v) {
    float2 f = upk(v); return f.x + f.y;
}
__device__ __forceinline__ uint32_t pkbf(float a, float b) {
    __nv_bfloat16 h0 = __float2bfloat16(a), h1 = __float2bfloat16(b);
    return (uint32_t)__bfloat16_as_ushort(h1) << 16 | __bfloat16_as_ushort(h0);
}
__device__ __forceinline__ void mma_bf16(float (&d)[4], uint32_t a0, uint32_t a1,
                                         uint32_t a2, uint32_t a3, uint32_t b0, uint32_t b1) {
    asm volatile("mma.sync.aligned.m16n8k16.row.col.f32.bf16.bf16.f32 "
                 "{%0,%1,%2,%3}, {%4,%5,%6,%7}, {%8,%9}, {%0,%1,%2,%3};"
                 : "+f"(d[0]), "+f"(d[1]), "+f"(d[2]), "+f"(d[3])
                 : "r"(a0), "r"(a1), "r"(a2), "r"(a3), "r"(b0), "r"(b1));
}

// ---------------- 0a) fold spatial-attention kernels ----------------
__global__ void prep_k(const float* __restrict__ c1a, const float* __restrict__ c1b,
                       const float* __restrict__ c2a, const float* __restrict__ c2b,
                       const float* __restrict__ c3) {
    int tid = threadIdx.x;
    float w3 = c3[0], w7 = c3[1];
    for (int e = tid; e < 49*32; e += 256) {
        int t = e >> 5, i = e & 31;
        int ty = t / 7 - 3, tx = t % 7 - 3;
        float s = 0.f;
        for (int o = 0; o < 32; o++)
            s += c2b[o] * c2a[((o*32 + i)*7 + (tx+3))*7 + (ty+3)];
        s *= w7;
        if (tx >= -1 && tx <= 1 && ty >= -1 && ty <= 1) {
            float s1 = 0.f;
            for (int o = 0; o < 32; o++)
                s1 += c1b[o] * c1a[((o*32 + i)*3 + (tx+1))*3 + (ty+1)];
            s += w3 * s1;
        }
        g_kcomb[e] = s;
    }
}

// ---------------- 0b) padded bf16 weight tiles for mma convs ----------------
__global__ void prep_wb_k(const float* __restrict__ w0p, const float* __restrict__ w1p) {
    int cv = blockIdx.x, tid = threadIdx.x;
    const float* W = cv ? w1p : w0p;
    __nv_bfloat16* out = g_Wb + cv*WB_ROWS*WB_STR;
    for (int e = tid; e < WB_ROWS*WB_STR; e += 256) {
        int row = e / WB_STR, k = e % WB_STR;
        int pass = row / 96, r2 = row % 96;
        int dh = r2 / 32, o = r2 % 32;
        float v = 0.f;
        if (k < 96) {
            int dw = k >> 5, i = k & 31;
            v = W[((o*32 + i)*3 + dw)*3 + dh];   // tap-swap for (0,3,2,1) world
        }
        __nv_bfloat16 hb = __float2bfloat16(v);
        out[e] = (pass == 0) ? hb : __float2bfloat16(v - __bfloat162float(hb));
    }
}

// ---------------- 1) stats stage 1 ----------------
__global__ __launch_bounds__(256) void stats1_k(const float* __restrict__ xfu,
                                                const float* __restrict__ xhsi) {
    __shared__ float sx[256*32];
    __shared__ float sh[8][32];
    int b = blockIdx.y, blk = blockIdx.x, tid = threadIdx.x;
    size_t base = ((size_t)b*NPIX + (size_t)blk*256) * 32;
    for (int k = 0; k < 32; k++) sx[k*256 + tid] = xfu[base + (size_t)k*256 + tid];
    {
        int c = tid & 31, grp = tid >> 5;
        float s = 0.f;
        for (int p = grp; p < 256; p += 8) s += xhsi[base + (size_t)p*32 + c];
        sh[grp][c] = s;
    }
    __syncthreads();
    int e0 = tid * 4;
    int i = e0 >> 5, j0 = e0 & 31;
    float4 a = make_float4(0.f, 0.f, 0.f, 0.f);
    const float4* sx4 = (const float4*)sx;
    for (int p = 0; p < 256; p++) {
        float xi = sx[p*32 + i];
        float4 xj = sx4[p*8 + (j0 >> 2)];
        a.x += xi * xj.x; a.y += xi * xj.y; a.z += xi * xj.z; a.w += xi * xj.w;
    }
    float* part = &g_part[((size_t)b*256 + blk) * 1056];
    ((float4*)part)[tid] = a;
    if (tid < 32) {
        float t = 0.f;
        for (int g = 0; g < 8; g++) t += sh[g][tid];
        part[1024 + tid] = t;
    }
}

// ---------------- 2) stats stage 2 ----------------
__global__ __launch_bounds__(256) void stats2_k(const float* __restrict__ Wq,
                                                const float* __restrict__ Wk,
                                                const float* __restrict__ fc1,
                                                const float* __restrict__ fc2,
                                                const float* __restrict__ projW,
                                                float* __restrict__ cm_out) {
    int b = blockIdx.x, tid = threadIdx.x;
    __shared__ float scov[1024], savg[32], sQ[1024], sK[1024];
    __shared__ float snq[32], snk[32], sG[256], sA[256], shid[32];
    for (int e = tid; e < 1024; e += 256) {
        float s = 0.f;
        for (int blk = 0; blk < 256; blk++) s += g_part[((size_t)b*256 + blk)*1056 + e];
        scov[e] = s;
    }
    if (tid < 32) {
        float s = 0.f;
        for (int blk = 0; blk < 256; blk++) s += g_part[((size_t)b*256 + blk)*1056 + 1024 + tid];
        savg[tid] = s * (1.f / (float)NPIX);
    }
    __syncthreads();
    for (int e = tid; e < 2048; e += 256) {
        int which = e >> 10; int r = e & 1023; int c = r >> 5, i = r & 31;
        const float* Wm = which ? Wk : Wq;
        float s = 0.f;
        for (int j = 0; j < 32; j++) s += scov[i*32 + j] * Wm[c*32 + j];
        if (which) sK[c*32 + i] = s; else sQ[c*32 + i] = s;
    }
    __syncthreads();
    if (tid < 32) { float s = 0.f; for (int i = 0; i < 32; i++) s += Wq[tid*32+i]*sQ[tid*32+i]; snq[tid] = sqrtf(fmaxf(s, 0.f)); }
    else if (tid < 64) { int c = tid-32; float s = 0.f; for (int i = 0; i < 32; i++) s += Wk[c*32+i]*sK[c*32+i]; snk[c] = sqrtf(fmaxf(s, 0.f)); }
    {
        int h = tid >> 6, d = (tid >> 3) & 7, e = tid & 7;
        float s = 0.f;
        for (int i = 0; i < 32; i++) s += Wk[(h*8+d)*32 + i] * sQ[(h*8+e)*32 + i];
        sG[tid] = s;
    }
    if (tid >= 64 && tid < 96) {
        int o = tid - 64; float s = 0.f;
        for (int i = 0; i < 32; i++) s += fc1[o*32 + i] * savg[i];
        shid[o] = fmaxf(s, 0.f);
    }
    __syncthreads();
    if (tid < 32) {
        int h = tid >> 3, d = tid & 7;
        float l[8]; float mx = -1e30f;
        float nk = fmaxf(snk[h*8 + d], 1e-12f);
        for (int e = 0; e < 8; e++) {
            float nq = fmaxf(snq[h*8 + e], 1e-12f);
            l[e] = sG[h*64 + d*8 + e] / (nk * nq);
            mx = fmaxf(mx, l[e]);
        }
        float ssum = 0.f;
        for (int e = 0; e < 8; e++) { l[e] = expf(l[e] - mx); ssum += l[e]; }
        float inv = 1.f / ssum;
        for (int e = 0; e < 8; e++) sA[h*64 + d*8 + e] = l[e] * inv;
    } else if (tid >= 128 && tid < 160) {
        int c = tid - 128; float s = 0.f;
        for (int i = 0; i < 32; i++) s += fc2[c*32 + i] * shid[i];
        float m = sigmoidf_(s);
        cm_out[b*32 + c] = m;
        g_cmask[b*32 + c] = m;
    }
    __syncthreads();
    for (int e = tid; e < 1024; e += 256) {
        int o = e >> 5, cp = e & 31, hp = cp >> 3, dp = cp & 7;
        float s = 0.f;
        for (int d = 0; d < 8; d++) s += projW[o*32 + hp*8 + d] * sA[hp*64 + d*8 + dp];
        g_M[b*1024 + e] = s;
    }
}

// ---------------- 3) spatial mask (R3 measured-best: 16w x 32h, 4 px/thread) ----------------
#define SM_TW 16
#define SM_TH 32
#define SM_CW 22
#define SM_CWP 23
#define SM_RH 38
#define SM_STR 36
#define SMASK_XF (SM_RH*SM_CWP*SM_STR)
#define SMASK_SMEM ((SMASK_XF + 49*32) * 4)

__global__ __launch_bounds__(128) void smask_k(const float* __restrict__ xmsi,
                                               float* __restrict__ sm_out) {
    extern __shared__ float dyn[];
    float* sx = dyn;
    float* kc = dyn + SMASK_XF;
    int tid = threadIdx.x, bx = blockIdx.x, by = blockIdx.y, b = blockIdx.z;
    for (int e = tid; e < 49*32; e += 128) kc[e] = g_kcomb[e];
    for (int slot = tid; slot < SM_RH*SM_CW; slot += 128) {
        int r = slot / SM_CW, c = slot % SM_CW;
        int gh = by*SM_TH + r - 3, gw = bx*SM_TW + c - 3;
        float4* dst = (float4*)&sx[(r*SM_CWP + c)*SM_STR];
        if ((unsigned)gh < (unsigned)HH && (unsigned)gw < (unsigned)WW) {
            const float4* src = (const float4*)(xmsi + (((size_t)b*HH + gh)*WW + gw)*32);
            #pragma unroll
            for (int i4 = 0; i4 < 8; i4++) dst[i4] = src[i4];
        } else {
            #pragma unroll
            for (int i4 = 0; i4 < 8; i4++) dst[i4] = make_float4(0.f,0.f,0.f,0.f);
        }
    }
    __syncthreads();
    int ty = tid >> 2, tq = (tid & 3) * 4;
    ull acc[4];
    #pragma unroll
    for (int p = 0; p < 4; p++) acc[p] = 0ull;
    #pragma unroll 1
    for (int cg = 0; cg < 8; cg++) {
        #pragma unroll 1
        for (int dy = 0; dy < 7; dy++) {
            ulonglong2 xw[10];
            #pragma unroll
            for (int j = 0; j < 10; j++)
                xw[j] = *(const ulonglong2*)&sx[((ty+dy)*SM_CWP + tq + j)*SM_STR + cg*4];
            #pragma unroll
            for (int dx = 0; dx < 7; dx++) {
                ulonglong2 wv = *(const ulonglong2*)&kc[(dy*7 + dx)*32 + cg*4];
                #pragma unroll
                for (int p = 0; p < 4; p++) {
                    fma2(acc[p], xw[dx+p].x, wv.x);
                    fma2(acc[p], xw[dx+p].y, wv.y);
                }
            }
        }
    }
    int h = by*SM_TH + ty;
    #pragma unroll
    for (int p = 0; p < 4; p++) {
        int w = bx*SM_TW + tq + p;
        float m = sigmoidf_(hadd2(acc[p]));
        g_smask[(size_t)b*NPIX + (size_t)h*WW + w] = m;
        sm_out[(size_t)b*NPIX + (size_t)w*HH + h] = m;
    }
}

// ---------------- 4) gated V -> split bf16 planes ----------------
__global__ __launch_bounds__(256) void vgated_k(const float* __restrict__ xfu,
                                                const float* __restrict__ Wv) {
    __shared__ float ws[32*32];  // ws[i*32+o] = Wv[o*32+i]
    __shared__ float cm[32];
    int tid = threadIdx.x, h = blockIdx.x, b = blockIdx.y;
    for (int e = tid; e < 1024; e += 256) {
        int o = e >> 5, i = e & 31;
        ws[i*32 + o] = Wv[e];
    }
    if (tid < 32) cm[tid] = g_cmask[b*32 + tid];
    __syncthreads();
    size_t pidx = (size_t)b*NPIX + (size_t)h*WW + tid;
    const float4* px = (const float4*)(xfu + pidx*32);
    ull acc[16];
    #pragma unroll
    for (int q = 0; q < 16; q++) acc[q] = 0ull;
    #pragma unroll
    for (int i4 = 0; i4 < 8; i4++) {
        float4 v = px[i4];
        #pragma unroll
        for (int i = 0; i < 4; i++) {
            ull a = pk2((&v.x)[i]);
            const ulonglong2* wr = (const ulonglong2*)&ws[(i4*4 + i)*32];
            #pragma unroll
            for (int q = 0; q < 8; q++) {
                ulonglong2 wv = wr[q];
                fma2(acc[2*q], a, wv.x);
                fma2(acc[2*q+1], a, wv.y);
            }
        }
    }
    float sm = g_smask[pidx];
    uint32_t hw[16], lw[16];
    #pragma unroll
    for (int q = 0; q < 16; q++) {
        float2 f = upk(acc[q]);
        float r0 = f.x * sm * cm[2*q], r1 = f.y * sm * cm[2*q+1];
        __nv_bfloat16 h0 = __float2bfloat16(r0), h1 = __float2bfloat16(r1);
        hw[q] = (uint32_t)__bfloat16_as_ushort(h1) << 16 | __bfloat16_as_ushort(h0);
        lw[q] = pkbf(r0 - __bfloat162float(h0), r1 - __bfloat162float(h1));
    }
    uint4* oh = (uint4*)(g_vg_hi + pidx*32);
    uint4* ol = (uint4*)(g_vg_lo + pidx*32);
    #pragma unroll
    for (int q4 = 0; q4 < 4; q4++) {
        oh[q4] = make_uint4(hw[q4*4], hw[q4*4+1], hw[q4*4+2], hw[q4*4+3]);
        ol[q4] = make_uint4(lw[q4*4], lw[q4*4+1], lw[q4*4+2], lw[q4*4+3]);
    }
}

// ---------------- 5) HMMA implicit-GEMM 3x3 conv ----------------
// block = 1 output row x 128 px, 128 threads (4 warps x 2 m16 tiles)
// mode 0: g_vg planes -> g_vspec fp32 (+x_hsi resid) + g_vs planes
// mode 1: g_vs planes -> g_tpos fp32 (bias + gelu)
// NOTE: all device arrays referenced INSIDE the kernel (host cannot pass
// __device__ symbol addresses directly — that was the R11 bug).
#define CM_COLS 130
#define CM_PSTR 72                          // bf16 slot: 32 hi + 32 lo + 8 pad
#define CM_XELEM (3*CM_COLS*CM_PSTR)        // 28080 bf16
#define CM_WELEM (WB_ROWS*WB_STR)           // 19968 bf16
#define CM_SMEM (CM_XELEM*2 + CM_WELEM*2 + 128)

__global__ __launch_bounds__(128) void convm_k(int mode,
                                               const float* __restrict__ resid,
                                               const float* __restrict__ bias) {
    extern __shared__ __align__(16) unsigned char smraw[];
    __nv_bfloat16* xs = (__nv_bfloat16*)smraw;
    __nv_bfloat16* wsm = xs + CM_XELEM;
    float* sb = (float*)(wsm + CM_WELEM);
    int tid = threadIdx.x;
    int b = blockIdx.z, h = blockIdx.y, w0 = blockIdx.x * 128;
    const __nv_bfloat16* inH = (mode == 0) ? g_vg_hi : g_vs_hi;
    const __nv_bfloat16* inL = (mode == 0) ? g_vg_lo : g_vs_lo;
    const __nv_bfloat16* wb = g_Wb + (size_t)mode*WB_ROWS*WB_STR;
    // weights -> smem (coalesced uint4)
    {
        const uint4* gw = (const uint4*)wb;
        uint4* sw = (uint4*)wsm;
        for (int e = tid; e < CM_WELEM/8; e += 128) sw[e] = gw[e];
    }
    if (tid < 32) sb[tid] = bias ? bias[tid] : 0.f;
    // x tile: 3 halo rows x 130 cols, hi plane ch 0..31, lo plane ch 32..63
    for (int f = tid; f < 3*CM_COLS*8; f += 128) {
        int cp = f >> 3, j = f & 7;
        int r = cp / CM_COLS, c = cp - r*CM_COLS;
        int gh = h - 1 + r, gw_ = w0 - 1 + c;
        int p = j >> 2, jj = j & 3;
        uint4 v = make_uint4(0,0,0,0);
        if ((unsigned)gh < (unsigned)HH && (unsigned)gw_ < (unsigned)WW) {
            const __nv_bfloat16* src = p ? inL : inH;
            v = ((const uint4*)(src + (((size_t)b*HH + gh)*WW + gw_)*32))[jj];
        }
        *(uint4*)&xs[(r*CM_COLS + c)*CM_PSTR + p*32 + jj*8] = v;
    }
    __syncthreads();
    int lane = tid & 31, warp = tid >> 5;
    int g = lane >> 2, t = lane & 3;
    size_t rowbase = ((size_t)b*HH + h)*WW;
    #pragma unroll 1
    for (int tile = 0; tile < 2; tile++) {
        int p0 = warp*32 + tile*16;
        float d0[4], d1[4], d2[4], d3[4];
        #pragma unroll
        for (int q = 0; q < 4; q++) { d0[q]=0.f; d1[q]=0.f; d2[q]=0.f; d3[q]=0.f; }
        #pragma unroll 1
        for (int dh = 0; dh < 3; dh++) {
            #pragma unroll 1
            for (int kc = 0; kc < 6; kc++) {
                int dw = kc >> 1, i0 = (kc & 1) << 4;
                const __nv_bfloat16* ar = &xs[(dh*CM_COLS + p0 + g + dw)*CM_PSTR + i0 + 2*t];
                uint32_t ah0 = *(const uint32_t*)ar;
                uint32_t ah1 = *(const uint32_t*)(ar + 8*CM_PSTR);
                uint32_t ah2 = *(const uint32_t*)(ar + 8);
                uint32_t ah3 = *(const uint32_t*)(ar + 8*CM_PSTR + 8);
                uint32_t al0 = *(const uint32_t*)(ar + 32);
                uint32_t al1 = *(const uint32_t*)(ar + 8*CM_PSTR + 32);
                uint32_t al2 = *(const uint32_t*)(ar + 40);
                uint32_t al3 = *(const uint32_t*)(ar + 8*CM_PSTR + 40);
                int kof = (dw << 5) + i0 + 2*t;
                #pragma unroll
                for (int nc = 0; nc < 4; nc++) {
                    const __nv_bfloat16* wr = &wsm[(dh*32 + nc*8 + g)*WB_STR + kof];
                    uint32_t bh0 = *(const uint32_t*)wr;
                    uint32_t bh1 = *(const uint32_t*)(wr + 8);
                    const __nv_bfloat16* wl = wr + 96*WB_STR;
                    uint32_t bl0 = *(const uint32_t*)wl;
                    uint32_t bl1 = *(const uint32_t*)(wl + 8);
                    float (&dd)[4] = (nc==0) ? d0 : (nc==1) ? d1 : (nc==2) ? d2 : d3;
                    mma_bf16(dd, ah0, ah1, ah2, ah3, bh0, bh1);
                    mma_bf16(dd, al0, al1, al2, al3, bh0, bh1);
                    mma_bf16(dd, ah0, ah1, ah2, ah3, bl0, bl1);
                }
            }
        }
        // epilogue: lane owns rows g, g+8; channels nc*8 + 2t, +1
        int px0 = w0 + p0 + g, px1 = px0 + 8;
        #pragma unroll
        for (int nc = 0; nc < 4; nc++) {
            const float* dd = (nc==0) ? d0 : (nc==1) ? d1 : (nc==2) ? d2 : d3;
            int ch = nc*8 + 2*t;
            float v0 = dd[0], v1 = dd[1];   // row g
            float u0 = dd[2], u1 = dd[3];   // row g+8
            size_t i0e = (rowbase + px0)*32 + ch;
            size_t i1e = (rowbase + px1)*32 + ch;
            if (mode == 0) {
                float2 r0 = *(const float2*)(resid + i0e);
                float2 r1 = *(const float2*)(resid + i1e);
                v0 += r0.x; v1 += r0.y; u0 += r1.x; u1 += r1.y;
                *(float2*)(g_vspec + i0e) = make_float2(v0, v1);
                *(float2*)(g_vspec + i1e) = make_float2(u0, u1);
                __nv_bfloat16 h0 = __float2bfloat16(v0), h1 = __float2bfloat16(v1);
                __nv_bfloat16 k0 = __float2bfloat16(u0), k1 = __float2bfloat16(u1);
                *(uint32_t*)(g_vs_hi + i0e) = (uint32_t)__bfloat16_as_ushort(h1) << 16 | __bfloat16_as_ushort(h0);
                *(uint32_t*)(g_vs_hi + i1e) = (uint32_t)__bfloat16_as_ushort(k1) << 16 | __bfloat16_as_ushort(k0);
                *(uint32_t*)(g_vs_lo + i0e) = pkbf(v0 - __bfloat162float(h0), v1 - __bfloat162float(h1));
                *(uint32_t*)(g_vs_lo + i1e) = pkbf(u0 - __bfloat162float(k0), u1 - __bfloat162float(k1));
            } else {
                v0 = gelu_exact(v0 + sb[ch]);   v1 = gelu_exact(v1 + sb[ch+1]);
                u0 = gelu_exact(u0 + sb[ch]);   u1 = gelu_exact(u1 + sb[ch+1]);
                *(float2*)(g_tpos + i0e) = make_float2(v0, v1);
                *(float2*)(g_tpos + i1e) = make_float2(u0, u1);
            }
        }
    }
}

// ---------------- 6) final (R10 proven): tiled FFMA2 conv + fused matvec ----------------
#define CT_CW 258
#define CT_TR 4
#define CT_XF (CT_TR*CT_CW*36)
__device__ __forceinline__ void load_tile4(float* sx, const float* __restrict__ in,
                                           int b, int h0, int tid) {
    for (int f = tid; f < CT_TR*CT_CW*8; f += 128) {
        int px = f >> 3, i4 = f & 7;
        int r = px / CT_CW, c = px - r*CT_CW;
        int gh = h0 - 1 + r, gw = c - 1;
        float4 v = make_float4(0.f, 0.f, 0.f, 0.f);
        if ((unsigned)gh < (unsigned)HH && (unsigned)gw < (unsigned)WW)
            v = ((const float4*)(in + (((size_t)b*HH + gh)*WW + gw)*32))[i4];
        *(float4*)&sx[px*36 + i4*4] = v;
    }
}
__device__ __forceinline__ void conv_half(ull (&acc)[4][8], const float* sx,
                                          const float* ws, int row, int base, int oh) {
    #pragma unroll 1
    for (int dh = 0; dh < 3; dh++) {
        const float* xrow = &sx[(row + dh)*CT_CW*36];
        #pragma unroll 1
        for (int i4 = 0; i4 < 8; i4++) {
            float4 xv[4][3];
            #pragma unroll
            for (int k = 0; k < 4; k++)
                #pragma unroll
                for (int dw = 0; dw < 3; dw++)
                    xv[k][dw] = *(const float4*)&xrow[(base + k*32 + dw)*36 + i4*4];
            #pragma unroll
            for (int i = 0; i < 4; i++) {
                ull a[4][3];
                #pragma unroll
                for (int k = 0; k < 4; k++)
                    #pragma unroll
                    for (int dw = 0; dw < 3; dw++)
                        a[k][dw] = pk2((&xv[k][dw].x)[i]);
                #pragma unroll
                for (int dw = 0; dw < 3; dw++) {
                    const ulonglong2* wp = (const ulonglong2*)&ws[(dh*3 + dw)*1024 + (i4*4 + i)*32 + oh*16];
                    ulonglong2 wA = wp[0], wB = wp[1];
                    #pragma unroll
                    for (int k = 0; k < 4; k++) {
                        fma2(acc[k][0], a[k][dw], wA.x);
                        fma2(acc[k][1], a[k][dw], wA.y);
                        fma2(acc[k][2], a[k][dw], wB.x);
                        fma2(acc[k][3], a[k][dw], wB.y);
                    }
                    ulonglong2 wC = wp[2], wD = wp[3];
                    #pragma unroll
                    for (int k = 0; k < 4; k++) {
                        fma2(acc[k][4], a[k][dw], wC.x);
                        fma2(acc[k][5], a[k][dw], wC.y);
                        fma2(acc[k][6], a[k][dw], wD.x);
                        fma2(acc[k][7], a[k][dw], wD.y);
                    }
                }
            }
        }
    }
}

#define FIN_SMEM ((CT_XF + 9216 + 1024 + 64)*4)
__global__ __launch_bounds__(128) void final_s_k(const float* __restrict__ w2src,
                                                 const float* __restrict__ b2,
                                                 const float* __restrict__ projb) {
    extern __shared__ float dyn[];
    float* sx = dyn;
    float* ws = dyn + CT_XF;
    float* wm = ws + 9216;
    float* sb2 = wm + 1024;
    float* spb = sb2 + 32;
    int tid = threadIdx.x, b = blockIdx.y, h0 = blockIdx.x * 2;
    for (int e = tid; e < 9216; e += 128) {
        int o = e & 31, i = (e >> 5) & 31, t = e >> 10;
        int dh = t / 3, dw = t % 3;
        ws[e] = w2src[((o*32 + i)*3 + dw)*3 + dh];
    }
    for (int e = tid; e < 1024; e += 128) {
        int c = e >> 5, o = e & 31;
        wm[c*32 + o] = g_M[b*1024 + o*32 + c];
    }
    if (tid < 32) { sb2[tid] = b2[tid]; spb[tid] = projb[tid]; }
    load_tile4(sx, g_tpos, b, h0, tid);
    __syncthreads();
    int row = tid >> 6;
    int base = ((tid >> 5) & 1) * 128 + (tid & 31);
    #pragma unroll 1
    for (int oh = 0; oh < 2; oh++) {
        ull acc[4][8];
        #pragma unroll
        for (int k = 0; k < 4; k++)
            #pragma unroll
            for (int q = 0; q < 8; q++)
                acc[k][q] = pkpair(sb2[oh*16 + 2*q], sb2[oh*16 + 2*q + 1]);
        conv_half(acc, sx, ws, row, base, oh);
        ull mv[4][8];
        #pragma unroll
        for (int k = 0; k < 4; k++)
            #pragma unroll
            for (int q = 0; q < 8; q++)
                mv[k][q] = pkpair(spb[oh*16 + 2*q], spb[oh*16 + 2*q + 1]);
        size_t prow = ((size_t)b*HH + h0 + row)*WW;
        #pragma unroll 1
        for (int i4 = 0; i4 < 8; i4++) {
            float4 v[4];
            #pragma unroll
            for (int k = 0; k < 4; k++)
                v[k] = ((const float4*)(g_vspec + (prow + base + k*32)*32))[i4];
            #pragma unroll
            for (int i = 0; i < 4; i++) {
                ull a[4];
                #pragma unroll
                for (int k = 0; k < 4; k++) a[k] = pk2((&v[k].x)[i]);
                const ulonglong2* wp = (const ulonglong2*)&wm[(i4*4 + i)*32 + oh*16];
                ulonglong2 wA = wp[0], wB = wp[1];
                #pragma unroll
                for (int k = 0; k < 4; k++) {
                    fma2(mv[k][0], a[k], wA.x);
                    fma2(mv[k][1], a[k], wA.y);
                    fma2(mv[k][2], a[k], wB.x);
                    fma2(mv[k][3], a[k], wB.y);
                }
                ulonglong2 wC = wp[2], wD = wp[3];
                #pragma unroll
                for (int k = 0; k < 4; k++) {
                    fma2(mv[k][4], a[k], wC.x);
                    fma2(mv[k][5], a[k], wC.y);
                    fma2(mv[k][6], a[k], wD.x);
                    fma2(mv[k][7], a[k], wD.y);
                }
            }
        }
        #pragma unroll
        for (int k = 0; k < 4; k++) {
            size_t pidx = (prow + base + k*32) * 32 + oh*16;
            float4* ob = (float4*)(g_outn + pidx);
            #pragma unroll
            for (int j = 0; j < 2; j++) {
                float2 c0 = upk(acc[k][j*4]),   c1 = upk(acc[k][j*4+1]);
                float2 c2 = upk(acc[k][j*4+2]), c3 = upk(acc[k][j*4+3]);
                float2 m0 = upk(mv[k][j*4]),    m1 = upk(mv[k][j*4+1]);
                float2 m2 = upk(mv[k][j*4+2]),  m3 = upk(mv[k][j*4+3]);
                ob[j*2]   = make_float4(gelu_exact(m0.x) + c0.x, gelu_exact(m0.y) + c0.y,
                                        gelu_exact(m1.x) + c1.x, gelu_exact(m1.y) + c1.y);
                ob[j*2+1] = make_float4(gelu_exact(m2.x) + c2.x, gelu_exact(m2.y) + c2.y,
                                        gelu_exact(m3.x) + c3.x, gelu_exact(m3.y) + c3.y);
            }
        }
    }
}

// ---------------- 7) transpose NHWC -> (b,c,w,h) ----------------
__global__ void transpose_k(float* __restrict__ out0) {
    __shared__ float tile[32][33];
    int b = blockIdx.z, w = blockIdx.y, h0 = blockIdx.x * 32;
    int tx = threadIdx.x, ty = threadIdx.y;
    tile[ty][tx] = g_outn[(((size_t)b*HH + (h0 + ty))*WW + w)*32 + tx];
    __syncthreads();
    out0[(((size_t)b*CC + ty)*WW + w)*HH + h0 + tx] = tile[tx][ty];
}

// ---------------- launch ----------------
extern "C" void kernel_launch(void* const* d_in, const int* in_sizes, int n_in,
                              void* d_out, int out_size) {
    const float* x_fu   = (const float*)d_in[0];
    const float* x_msi  = (const float*)d_in[1];
    const float* x_hsi  = (const float*)d_in[2];
    const float* Wq     = (const float*)d_in[3];
    const float* Wk     = (const float*)d_in[4];
    const float* Wv     = (const float*)d_in[5];
    const float* proj_W = (const float*)d_in[6];
    const float* proj_b = (const float*)d_in[7];
    const float* pos1_W = (const float*)d_in[8];
    const float* pos1_b = (const float*)d_in[9];
    const float* pos2_W = (const float*)d_in[10];
    const float* pos2_b = (const float*)d_in[11];
    const float* ca_fc1 = (const float*)d_in[12];
    const float* ca_fc2 = (const float*)d_in[13];
    const float* sa_c1a = (const float*)d_in[14];
    const float* sa_c1b = (const float*)d_in[15];
    const float* sa_c2a = (const float*)d_in[16];
    const float* sa_c2b = (const float*)d_in[17];
    const float* sa_c3  = (const float*)d_in[18];
    const float* attn_W = (const float*)d_in[19];

    float* out0   = (float*)d_out;
    float* cm_out = out0 + IMG_ELEMS;
    float* sm_out = cm_out + BB*CC;

    cudaFuncSetAttribute(smask_k,   cudaFuncAttributeMaxDynamicSharedMemorySize, SMASK_SMEM);
    cudaFuncSetAttribute(convm_k,   cudaFuncAttributeMaxDynamicSharedMemorySize, CM_SMEM);
    cudaFuncSetAttribute(final_s_k, cudaFuncAttributeMaxDynamicSharedMemorySize, FIN_SMEM);

    prep_k   <<<1, 256>>>(sa_c1a, sa_c1b, sa_c2a, sa_c2b, sa_c3);
    prep_wb_k<<<2, 256>>>(attn_W, pos1_W);
    stats1_k <<<dim3(256, BB), 256>>>(x_fu, x_hsi);
    stats2_k <<<BB, 256>>>(Wq, Wk, ca_fc1, ca_fc2, proj_W, cm_out);
    smask_k  <<<dim3(WW/SM_TW, HH/SM_TH, BB), 128, SMASK_SMEM>>>(x_msi, sm_out);
    vgated_k <<<dim3(HH, BB), 256>>>(x_fu, Wv);

    dim3 cg(WW/128, HH, BB);
    convm_k<<<cg, 128, CM_SMEM>>>(0, x_hsi, (const float*)nullptr);
    convm_k<<<cg, 128, CM_SMEM>>>(1, (const float*)nullptr, pos1_b);
    final_s_k<<<dim3(HH/2, BB), 128, FIN_SMEM>>>(pos2_W, pos2_b, proj_b);
    transpose_k<<<dim3(HH/32, WW, BB), dim3(32, 32)>>>(out0);
}

// round 13
// speedup vs baseline: 1.4739x; 1.0418x over previous
#include <cuda_runtime.h>
#include <cuda_bf16.h>
#include <stdint.h>
#include <math.h>

// ---------------- problem constants ----------------
#define BB 4
#define HH 256
#define WW 256
#define CC 32
#define NPIX (HH*WW)            // 65536
#define IMG_ELEMS (BB*NPIX*CC)  // 8388608

typedef unsigned long long ull;

// ---------------- device scratch ----------------
__device__ float g_part[BB*256*1056];
__device__ float g_cov[BB*1056];
__device__ float g_cmask[BB*CC];
__device__ float g_smask[BB*NPIX];
__device__ float g_kcomb[49*32];
__device__ float g_vspec[IMG_ELEMS];
__device__ float g_outn[IMG_ELEMS];
__device__ __nv_bfloat16 g_vg_hi[IMG_ELEMS], g_vg_lo[IMG_ELEMS];
__device__ __nv_bfloat16 g_vs_hi[IMG_ELEMS], g_vs_lo[IMG_ELEMS];
__device__ __nv_bfloat16 g_tp_hi[IMG_ELEMS], g_tp_lo[IMG_ELEMS];
// padded bf16 weight tiles for mma convs: [conv 3][pass 2][dh 3][o 32][k 104]
#define WB_ROWS (6*32)
#define WB_STR  104
__device__ __nv_bfloat16 g_Wb[3*WB_ROWS*WB_STR];
// per-batch split M tiles: [b][pass 2][o 32][k 40]
#define MB_ELEM 2560
__device__ __nv_bfloat16 g_Mbt[BB*MB_ELEM];

__device__ __forceinline__ float gelu_exact(float x) {
    return 0.5f * x * (1.0f + erff(x * 0.70710678118654752f));
}
__device__ __forceinline__ float sigmoidf_(float x) {
    return 1.0f / (1.0f + expf(-x));
}

// ---------------- packed f32x2 helpers ----------------
__device__ __forceinline__ void fma2(ull& c, ull a, ull b) {
    asm("fma.rn.f32x2 %0, %1, %2, %0;" : "+l"(c) : "l"(a), "l"(b));
}
__device__ __forceinline__ ull pk2(float x) {
    ull r; asm("mov.b64 %0, {%1, %1};" : "=l"(r) : "f"(x)); return r;
}
__device__ __forceinline__ float2 upk(ull v) {
    float2 f; asm("mov.b64 {%0, %1}, %2;" : "=f"(f.x), "=f"(f.y) : "l"(v)); return f;
}
__device__ __forceinline__ float hadd2(ull v) {
    float2 f = upk(v); return f.x + f.y;
}
__device__ __forceinline__ uint32_t pkbf(float a, float b) {
    __nv_bfloat16 h0 = __float2bfloat16(a), h1 = __float2bfloat16(b);
    return (uint32_t)__bfloat16_as_ushort(h1) << 16 | __bfloat16_as_ushort(h0);
}
__device__ __forceinline__ void mma_bf16(float (&d)[4], uint32_t a0, uint32_t a1,
                                         uint32_t a2, uint32_t a3, uint32_t b0, uint32_t b1) {
    asm volatile("mma.sync.aligned.m16n8k16.row.col.f32.bf16.bf16.f32 "
                 "{%0,%1,%2,%3}, {%4,%5,%6,%7}, {%8,%9}, {%0,%1,%2,%3};"
                 : "+f"(d[0]), "+f"(d[1]), "+f"(d[2]), "+f"(d[3])
                 : "r"(a0), "r"(a1), "r"(a2), "r"(a3), "r"(b0), "r"(b1));
}

// ---------------- 0a) fold spatial-attention kernels ----------------
__global__ void prep_k(const float* __restrict__ c1a, const float* __restrict__ c1b,
                       const float* __restrict__ c2a, const float* __restrict__ c2b,
                       const float* __restrict__ c3) {
    int tid = threadIdx.x;
    float w3 = c3[0], w7 = c3[1];
    for (int e = tid; e < 49*32; e += 256) {
        int t = e >> 5, i = e & 31;
        int ty = t / 7 - 3, tx = t % 7 - 3;
        float s = 0.f;
        for (int o = 0; o < 32; o++)
            s += c2b[o] * c2a[((o*32 + i)*7 + (tx+3))*7 + (ty+3)];
        s *= w7;
        if (tx >= -1 && tx <= 1 && ty >= -1 && ty <= 1) {
            float s1 = 0.f;
            for (int o = 0; o < 32; o++)
                s1 += c1b[o] * c1a[((o*32 + i)*3 + (tx+1))*3 + (ty+1)];
            s += w3 * s1;
        }
        g_kcomb[e] = s;
    }
}

// ---------------- 0b) padded bf16 weight tiles for mma convs ----------------
__global__ void prep_wb_k(const float* __restrict__ w0p, const float* __restrict__ w1p,
                          const float* __restrict__ w2p) {
    int cv = blockIdx.x, tid = threadIdx.x;
    const float* W = (cv == 0) ? w0p : ((cv == 1) ? w1p : w2p);
    __nv_bfloat16* out = g_Wb + (size_t)cv*WB_ROWS*WB_STR;
    for (int e = tid; e < WB_ROWS*WB_STR; e += 256) {
        int row = e / WB_STR, k = e % WB_STR;
        int pass = row / 96, r2 = row % 96;
        int dh = r2 / 32, o = r2 % 32;
        float v = 0.f;
        if (k < 96) {
            int dw = k >> 5, i = k & 31;
            v = W[((o*32 + i)*3 + dw)*3 + dh];   // tap-swap for (0,3,2,1) world
        }
        __nv_bfloat16 hb = __float2bfloat16(v);
        out[e] = (pass == 0) ? hb : __float2bfloat16(v - __bfloat162float(hb));
    }
}

// ---------------- 1) stats stage 1 ----------------
__global__ __launch_bounds__(256) void stats1_k(const float* __restrict__ xfu,
                                                const float* __restrict__ xhsi) {
    __shared__ float sx[256*32];
    __shared__ float sh[8][32];
    int b = blockIdx.y, blk = blockIdx.x, tid = threadIdx.x;
    size_t base = ((size_t)b*NPIX + (size_t)blk*256) * 32;
    for (int k = 0; k < 32; k++) sx[k*256 + tid] = xfu[base + (size_t)k*256 + tid];
    {
        int c = tid & 31, grp = tid >> 5;
        float s = 0.f;
        for (int p = grp; p < 256; p += 8) s += xhsi[base + (size_t)p*32 + c];
        sh[grp][c] = s;
    }
    __syncthreads();
    int e0 = tid * 4;
    int i = e0 >> 5, j0 = e0 & 31;
    float4 a = make_float4(0.f, 0.f, 0.f, 0.f);
    const float4* sx4 = (const float4*)sx;
    for (int p = 0; p < 256; p++) {
        float xi = sx[p*32 + i];
        float4 xj = sx4[p*8 + (j0 >> 2)];
        a.x += xi * xj.x; a.y += xi * xj.y; a.z += xi * xj.z; a.w += xi * xj.w;
    }
    float* part = &g_part[((size_t)b*256 + blk) * 1056];
    ((float4*)part)[tid] = a;
    if (tid < 32) {
        float t = 0.f;
        for (int g = 0; g < 8; g++) t += sh[g][tid];
        part[1024 + tid] = t;
    }
}

// ---------------- 1b) parallel reduce of partials ----------------
__global__ __launch_bounds__(256) void red_k() {
    __shared__ float sred[8][32];
    int b = blockIdx.y, e0 = blockIdx.x * 32;
    int lane = threadIdx.x & 31, gr = threadIdx.x >> 5;
    float s = 0.f;
    for (int blk = gr; blk < 256; blk += 8)
        s += g_part[((size_t)b*256 + blk)*1056 + e0 + lane];
    sred[gr][lane] = s;
    __syncthreads();
    if (threadIdx.x < 32) {
        float t = 0.f;
        #pragma unroll
        for (int g = 0; g < 8; g++) t += sred[g][lane];
        g_cov[b*1056 + e0 + lane] = t;
    }
}

// ---------------- 2) stats stage 2 ----------------
__global__ __launch_bounds__(256) void stats2_k(const float* __restrict__ Wq,
                                                const float* __restrict__ Wk,
                                                const float* __restrict__ fc1,
                                                const float* __restrict__ fc2,
                                                const float* __restrict__ projW,
                                                float* __restrict__ cm_out) {
    int b = blockIdx.x, tid = threadIdx.x;
    __shared__ float scov[1024], savg[32], sQ[1024], sK[1024];
    __shared__ float snq[32], snk[32], sG[256], sA[256], shid[32];
    for (int e = tid; e < 1024; e += 256) scov[e] = g_cov[b*1056 + e];
    if (tid < 32) savg[tid] = g_cov[b*1056 + 1024 + tid] * (1.f / (float)NPIX);
    __syncthreads();
    for (int e = tid; e < 2048; e += 256) {
        int which = e >> 10; int r = e & 1023; int c = r >> 5, i = r & 31;
        const float* Wm = which ? Wk : Wq;
        float s = 0.f;
        for (int j = 0; j < 32; j++) s += scov[i*32 + j] * Wm[c*32 + j];
        if (which) sK[c*32 + i] = s; else sQ[c*32 + i] = s;
    }
    __syncthreads();
    if (tid < 32) { float s = 0.f; for (int i = 0; i < 32; i++) s += Wq[tid*32+i]*sQ[tid*32+i]; snq[tid] = sqrtf(fmaxf(s, 0.f)); }
    else if (tid < 64) { int c = tid-32; float s = 0.f; for (int i = 0; i < 32; i++) s += Wk[c*32+i]*sK[c*32+i]; snk[c] = sqrtf(fmaxf(s, 0.f)); }
    {
        int h = tid >> 6, d = (tid >> 3) & 7, e = tid & 7;
        float s = 0.f;
        for (int i = 0; i < 32; i++) s += Wk[(h*8+d)*32 + i] * sQ[(h*8+e)*32 + i];
        sG[tid] = s;
    }
    if (tid >= 64 && tid < 96) {
        int o = tid - 64; float s = 0.f;
        for (int i = 0; i < 32; i++) s += fc1[o*32 + i] * savg[i];
        shid[o] = fmaxf(s, 0.f);
    }
    __syncthreads();
    if (tid < 32) {
        int h = tid >> 3, d = tid & 7;
        float l[8]; float mx = -1e30f;
        float nk = fmaxf(snk[h*8 + d], 1e-12f);
        for (int e = 0; e < 8; e++) {
            float nq = fmaxf(snq[h*8 + e], 1e-12f);
            l[e] = sG[h*64 + d*8 + e] / (nk * nq);
            mx = fmaxf(mx, l[e]);
        }
        float ssum = 0.f;
        for (int e = 0; e < 8; e++) { l[e] = expf(l[e] - mx); ssum += l[e]; }
        float inv = 1.f / ssum;
        for (int e = 0; e < 8; e++) sA[h*64 + d*8 + e] = l[e] * inv;
    } else if (tid >= 128 && tid < 160) {
        int c = tid - 128; float s = 0.f;
        for (int i = 0; i < 32; i++) s += fc2[c*32 + i] * shid[i];
        float m = sigmoidf_(s);
        cm_out[b*32 + c] = m;
        g_cmask[b*32 + c] = m;
    }
    __syncthreads();
    // M = projW @ blockdiag(A), written as split-bf16 padded tile [pass][o][40]
    for (int e = tid; e < 1024; e += 256) {
        int o = e >> 5, cp = e & 31, hp = cp >> 3, dp = cp & 7;
        float s = 0.f;
        for (int d = 0; d < 8; d++) s += projW[o*32 + hp*8 + d] * sA[hp*64 + d*8 + dp];
        __nv_bfloat16 hb = __float2bfloat16(s);
        g_Mbt[b*MB_ELEM + o*40 + cp] = hb;
        g_Mbt[b*MB_ELEM + 1280 + o*40 + cp] = __float2bfloat16(s - __bfloat162float(hb));
    }
}

// ---------------- 3) spatial mask (R3 measured-best: 16w x 32h, 4 px/thread) ----------------
#define SM_TW 16
#define SM_TH 32
#define SM_CW 22
#define SM_CWP 23
#define SM_RH 38
#define SM_STR 36
#define SMASK_XF (SM_RH*SM_CWP*SM_STR)
#define SMASK_SMEM ((SMASK_XF + 49*32) * 4)

__global__ __launch_bounds__(128) void smask_k(const float* __restrict__ xmsi,
                                               float* __restrict__ sm_out) {
    extern __shared__ float dyn[];
    float* sx = dyn;
    float* kc = dyn + SMASK_XF;
    int tid = threadIdx.x, bx = blockIdx.x, by = blockIdx.y, b = blockIdx.z;
    for (int e = tid; e < 49*32; e += 128) kc[e] = g_kcomb[e];
    for (int slot = tid; slot < SM_RH*SM_CW; slot += 128) {
        int r = slot / SM_CW, c = slot % SM_CW;
        int gh = by*SM_TH + r - 3, gw = bx*SM_TW + c - 3;
        float4* dst = (float4*)&sx[(r*SM_CWP + c)*SM_STR];
        if ((unsigned)gh < (unsigned)HH && (unsigned)gw < (unsigned)WW) {
            const float4* src = (const float4*)(xmsi + (((size_t)b*HH + gh)*WW + gw)*32);
            #pragma unroll
            for (int i4 = 0; i4 < 8; i4++) dst[i4] = src[i4];
        } else {
            #pragma unroll
            for (int i4 = 0; i4 < 8; i4++) dst[i4] = make_float4(0.f,0.f,0.f,0.f);
        }
    }
    __syncthreads();
    int ty = tid >> 2, tq = (tid & 3) * 4;
    ull acc[4];
    #pragma unroll
    for (int p = 0; p < 4; p++) acc[p] = 0ull;
    #pragma unroll 1
    for (int cg = 0; cg < 8; cg++) {
        #pragma unroll 1
        for (int dy = 0; dy < 7; dy++) {
            ulonglong2 xw[10];
            #pragma unroll
            for (int j = 0; j < 10; j++)
                xw[j] = *(const ulonglong2*)&sx[((ty+dy)*SM_CWP + tq + j)*SM_STR + cg*4];
            #pragma unroll
            for (int dx = 0; dx < 7; dx++) {
                ulonglong2 wv = *(const ulonglong2*)&kc[(dy*7 + dx)*32 + cg*4];
                #pragma unroll
                for (int p = 0; p < 4; p++) {
                    fma2(acc[p], xw[dx+p].x, wv.x);
                    fma2(acc[p], xw[dx+p].y, wv.y);
                }
            }
        }
    }
    int h = by*SM_TH + ty;
    #pragma unroll
    for (int p = 0; p < 4; p++) {
        int w = bx*SM_TW + tq + p;
        float m = sigmoidf_(hadd2(acc[p]));
        g_smask[(size_t)b*NPIX + (size_t)h*WW + w] = m;
        sm_out[(size_t)b*NPIX + (size_t)w*HH + h] = m;
    }
}

// ---------------- 4) gated V -> split bf16 planes ----------------
__global__ __launch_bounds__(256) void vgated_k(const float* __restrict__ xfu,
                                                const float* __restrict__ Wv) {
    __shared__ float ws[32*32];  // ws[i*32+o] = Wv[o*32+i]
    __shared__ float cm[32];
    int tid = threadIdx.x, h = blockIdx.x, b = blockIdx.y;
    for (int e = tid; e < 1024; e += 256) {
        int o = e >> 5, i = e & 31;
        ws[i*32 + o] = Wv[e];
    }
    if (tid < 32) cm[tid] = g_cmask[b*32 + tid];
    __syncthreads();
    size_t pidx = (size_t)b*NPIX + (size_t)h*WW + tid;
    const float4* px = (const float4*)(xfu + pidx*32);
    ull acc[16];
    #pragma unroll
    for (int q = 0; q < 16; q++) acc[q] = 0ull;
    #pragma unroll
    for (int i4 = 0; i4 < 8; i4++) {
        float4 v = px[i4];
        #pragma unroll
        for (int i = 0; i < 4; i++) {
            ull a = pk2((&v.x)[i]);
            const ulonglong2* wr = (const ulonglong2*)&ws[(i4*4 + i)*32];
            #pragma unroll
            for (int q = 0; q < 8; q++) {
                ulonglong2 wv = wr[q];
                fma2(acc[2*q], a, wv.x);
                fma2(acc[2*q+1], a, wv.y);
            }
        }
    }
    float sm = g_smask[pidx];
    uint32_t hw[16], lw[16];
    #pragma unroll
    for (int q = 0; q < 16; q++) {
        float2 f = upk(acc[q]);
        float r0 = f.x * sm * cm[2*q], r1 = f.y * sm * cm[2*q+1];
        __nv_bfloat16 h0 = __float2bfloat16(r0), h1 = __float2bfloat16(r1);
        hw[q] = (uint32_t)__bfloat16_as_ushort(h1) << 16 | __bfloat16_as_ushort(h0);
        lw[q] = pkbf(r0 - __bfloat162float(h0), r1 - __bfloat162float(h1));
    }
    uint4* oh = (uint4*)(g_vg_hi + pidx*32);
    uint4* ol = (uint4*)(g_vg_lo + pidx*32);
    #pragma unroll
    for (int q4 = 0; q4 < 4; q4++) {
        oh[q4] = make_uint4(hw[q4*4], hw[q4*4+1], hw[q4*4+2], hw[q4*4+3]);
        ol[q4] = make_uint4(lw[q4*4], lw[q4*4+1], lw[q4*4+2], lw[q4*4+3]);
    }
}

// ---------------- 5) HMMA implicit-GEMM 3x3 conv (+ fused final matvec in mode 2) ----------------
// block = 1 output row x 128 px, 128 threads (4 warps x 2 m16 tiles)
// mode 0: vg planes -> g_vspec fp32 (+x_hsi resid) + vs planes
// mode 1: vs planes -> tp planes (pos1 bias + gelu)
// mode 2: tp planes -> conv(pos2) [+ HMMA matvec M@vspec via vs planes] -> g_outn
#define CM_COLS 130
#define CM_PSTR 72                          // bf16 slot: 32 hi + 32 lo + 8 pad
#define CM_XELEM (3*CM_COLS*CM_PSTR)        // 28080 bf16
#define CM_WELEM (WB_ROWS*WB_STR)           // 19968 bf16
#define CM_SMEM  (CM_XELEM*2 + CM_WELEM*2 + 256)
#define CM_SMEM2 (CM_SMEM + 128*72*2 + MB_ELEM*2)

__global__ __launch_bounds__(128) void convm_k(int mode,
                                               const float* __restrict__ resid,
                                               const float* __restrict__ bias,
                                               const float* __restrict__ bias2) {
    extern __shared__ __align__(16) unsigned char smraw[];
    __nv_bfloat16* xs = (__nv_bfloat16*)smraw;
    __nv_bfloat16* wsm = xs + CM_XELEM;
    float* sb = (float*)(wsm + CM_WELEM);
    float* spb = sb + 32;
    __nv_bfloat16* vstile = (__nv_bfloat16*)(spb + 32);
    __nv_bfloat16* msm = vstile + 128*72;
    int tid = threadIdx.x;
    int b = blockIdx.z, h = blockIdx.y, w0 = blockIdx.x * 128;
    size_t rowbase = ((size_t)b*HH + h)*WW;
    const __nv_bfloat16* inH = (mode == 0) ? g_vg_hi : ((mode == 1) ? g_vs_hi : g_tp_hi);
    const __nv_bfloat16* inL = (mode == 0) ? g_vg_lo : ((mode == 1) ? g_vs_lo : g_tp_lo);
    const __nv_bfloat16* wb = g_Wb + (size_t)mode*WB_ROWS*WB_STR;
    // weights -> smem
    {
        const uint4* gw = (const uint4*)wb;
        uint4* sw = (uint4*)wsm;
        for (int e = tid; e < CM_WELEM/8; e += 128) sw[e] = gw[e];
    }
    if (tid < 32) sb[tid] = bias ? bias[tid] : 0.f;
    else if (tid < 64 && mode == 2) spb[tid-32] = bias2[tid-32];
    // x tile: 3 halo rows x 130 cols, hi plane ch 0..31, lo plane ch 32..63
    for (int f = tid; f < 3*CM_COLS*8; f += 128) {
        int cp = f >> 3, j = f & 7;
        int r = cp / CM_COLS, c = cp - r*CM_COLS;
        int gh = h - 1 + r, gw_ = w0 - 1 + c;
        int p = j >> 2, jj = j & 3;
        uint4 v = make_uint4(0,0,0,0);
        if ((unsigned)gh < (unsigned)HH && (unsigned)gw_ < (unsigned)WW) {
            const __nv_bfloat16* src = p ? inL : inH;
            v = ((const uint4*)(src + (((size_t)b*HH + gh)*WW + gw_)*32))[jj];
        }
        *(uint4*)&xs[(r*CM_COLS + c)*CM_PSTR + p*32 + jj*8] = v;
    }
    if (mode == 2) {
        // vs planes for the 128 center pixels (matvec A)
        for (int f = tid; f < 128*8; f += 128) {
            int px = f >> 3, j = f & 7, p = j >> 2, jj = j & 3;
            const __nv_bfloat16* src = p ? g_vs_lo : g_vs_hi;
            uint4 v = ((const uint4*)(src + (rowbase + w0 + px)*32))[jj];
            *(uint4*)&vstile[px*72 + p*32 + jj*8] = v;
        }
        // M tile
        const uint4* gm = (const uint4*)(g_Mbt + (size_t)b*MB_ELEM);
        uint4* sm2 = (uint4*)msm;
        for (int e = tid; e < MB_ELEM/8; e += 128) sm2[e] = gm[e];
    }
    __syncthreads();
    int lane = tid & 31, warp = tid >> 5;
    int g = lane >> 2, t = lane & 3;
    #pragma unroll 1
    for (int tile = 0; tile < 2; tile++) {
        int p0 = warp*32 + tile*16;
        float d0[4], d1[4], d2[4], d3[4];
        #pragma unroll
        for (int q = 0; q < 4; q++) { d0[q]=0.f; d1[q]=0.f; d2[q]=0.f; d3[q]=0.f; }
        #pragma unroll 1
        for (int dh = 0; dh < 3; dh++) {
            #pragma unroll 1
            for (int kc = 0; kc < 6; kc++) {
                int dw = kc >> 1, i0 = (kc & 1) << 4;
                const __nv_bfloat16* ar = &xs[(dh*CM_COLS + p0 + g + dw)*CM_PSTR + i0 + 2*t];
                uint32_t ah0 = *(const uint32_t*)ar;
                uint32_t ah1 = *(const uint32_t*)(ar + 8*CM_PSTR);
                uint32_t ah2 = *(const uint32_t*)(ar + 8);
                uint32_t ah3 = *(const uint32_t*)(ar + 8*CM_PSTR + 8);
                uint32_t al0 = *(const uint32_t*)(ar + 32);
                uint32_t al1 = *(const uint32_t*)(ar + 8*CM_PSTR + 32);
                uint32_t al2 = *(const uint32_t*)(ar + 40);
                uint32_t al3 = *(const uint32_t*)(ar + 8*CM_PSTR + 40);
                int kof = (dw << 5) + i0 + 2*t;
                #pragma unroll
                for (int nc = 0; nc < 4; nc++) {
                    const __nv_bfloat16* wr = &wsm[(dh*32 + nc*8 + g)*WB_STR + kof];
                    uint32_t bh0 = *(const uint32_t*)wr;
                    uint32_t bh1 = *(const uint32_t*)(wr + 8);
                    const __nv_bfloat16* wl = wr + 96*WB_STR;
                    uint32_t bl0 = *(const uint32_t*)wl;
                    uint32_t bl1 = *(const uint32_t*)(wl + 8);
                    float (&dd)[4] = (nc==0) ? d0 : (nc==1) ? d1 : (nc==2) ? d2 : d3;
                    mma_bf16(dd, ah0, ah1, ah2, ah3, bh0, bh1);
                    mma_bf16(dd, al0, al1, al2, al3, bh0, bh1);
                    mma_bf16(dd, ah0, ah1, ah2, ah3, bl0, bl1);
                }
            }
        }
        // matvec accumulators (mode 2)
        float m0[4], m1[4], m2[4], m3[4];
        #pragma unroll
        for (int q = 0; q < 4; q++) { m0[q]=0.f; m1[q]=0.f; m2[q]=0.f; m3[q]=0.f; }
        if (mode == 2) {
            #pragma unroll
            for (int kc = 0; kc < 2; kc++) {
                int i0 = kc << 4;
                const __nv_bfloat16* ar = &vstile[(p0 + g)*72 + i0 + 2*t];
                uint32_t ah0 = *(const uint32_t*)ar;
                uint32_t ah1 = *(const uint32_t*)(ar + 8*72);
                uint32_t ah2 = *(const uint32_t*)(ar + 8);
                uint32_t ah3 = *(const uint32_t*)(ar + 8*72 + 8);
                uint32_t al0 = *(const uint32_t*)(ar + 32);
                uint32_t al1 = *(const uint32_t*)(ar + 8*72 + 32);
                uint32_t al2 = *(const uint32_t*)(ar + 40);
                uint32_t al3 = *(const uint32_t*)(ar + 8*72 + 40);
                int kof = i0 + 2*t;
                #pragma unroll
                for (int nc = 0; nc < 4; nc++) {
                    const __nv_bfloat16* wr = &msm[(nc*8 + g)*40 + kof];
                    uint32_t bh0 = *(const uint32_t*)wr;
                    uint32_t bh1 = *(const uint32_t*)(wr + 8);
                    const __nv_bfloat16* wl = wr + 1280;
                    uint32_t bl0 = *(const uint32_t*)wl;
                    uint32_t bl1 = *(const uint32_t*)(wl + 8);
                    float (&mm)[4] = (nc==0) ? m0 : (nc==1) ? m1 : (nc==2) ? m2 : m3;
                    mma_bf16(mm, ah0, ah1, ah2, ah3, bh0, bh1);
                    mma_bf16(mm, al0, al1, al2, al3, bh0, bh1);
                    mma_bf16(mm, ah0, ah1, ah2, ah3, bl0, bl1);
                }
            }
        }
        // epilogue: lane owns rows g, g+8; channels nc*8 + 2t, +1
        int px0 = w0 + p0 + g, px1 = px0 + 8;
        #pragma unroll
        for (int nc = 0; nc < 4; nc++) {
            const float* dd = (nc==0) ? d0 : (nc==1) ? d1 : (nc==2) ? d2 : d3;
            const float* mm = (nc==0) ? m0 : (nc==1) ? m1 : (nc==2) ? m2 : m3;
            int ch = nc*8 + 2*t;
            float v0 = dd[0], v1 = dd[1];   // row g
            float u0 = dd[2], u1 = dd[3];   // row g+8
            size_t i0e = (rowbase + px0)*32 + ch;
            size_t i1e = (rowbase + px1)*32 + ch;
            if (mode == 0) {
                float2 r0 = *(const float2*)(resid + i0e);
                float2 r1 = *(const float2*)(resid + i1e);
                v0 += r0.x; v1 += r0.y; u0 += r1.x; u1 += r1.y;
                *(float2*)(g_vspec + i0e) = make_float2(v0, v1);
                *(float2*)(g_vspec + i1e) = make_float2(u0, u1);
                __nv_bfloat16 h0 = __float2bfloat16(v0), h1 = __float2bfloat16(v1);
                __nv_bfloat16 k0 = __float2bfloat16(u0), k1 = __float2bfloat16(u1);
                *(uint32_t*)(g_vs_hi + i0e) = (uint32_t)__bfloat16_as_ushort(h1) << 16 | __bfloat16_as_ushort(h0);
                *(uint32_t*)(g_vs_hi + i1e) = (uint32_t)__bfloat16_as_ushort(k1) << 16 | __bfloat16_as_ushort(k0);
                *(uint32_t*)(g_vs_lo + i0e) = pkbf(v0 - __bfloat162float(h0), v1 - __bfloat162float(h1));
                *(uint32_t*)(g_vs_lo + i1e) = pkbf(u0 - __bfloat162float(k0), u1 - __bfloat162float(k1));
            } else if (mode == 1) {
                v0 = gelu_exact(v0 + sb[ch]);   v1 = gelu_exact(v1 + sb[ch+1]);
                u0 = gelu_exact(u0 + sb[ch]);   u1 = gelu_exact(u1 + sb[ch+1]);
                __nv_bfloat16 h0 = __float2bfloat16(v0), h1 = __float2bfloat16(v1);
                __nv_bfloat16 k0 = __float2bfloat16(u0), k1 = __float2bfloat16(u1);
                *(uint32_t*)(g_tp_hi + i0e) = (uint32_t)__bfloat16_as_ushort(h1) << 16 | __bfloat16_as_ushort(h0);
                *(uint32_t*)(g_tp_hi + i1e) = (uint32_t)__bfloat16_as_ushort(k1) << 16 | __bfloat16_as_ushort(k0);
                *(uint32_t*)(g_tp_lo + i0e) = pkbf(v0 - __bfloat162float(h0), v1 - __bfloat162float(h1));
                *(uint32_t*)(g_tp_lo + i1e) = pkbf(u0 - __bfloat162float(k0), u1 - __bfloat162float(k1));
            } else {
                // out = gelu(matvec + proj_b) + pos2_b + conv
                v0 += gelu_exact(mm[0] + spb[ch])   + sb[ch];
                v1 += gelu_exact(mm[1] + spb[ch+1]) + sb[ch+1];
                u0 += gelu_exact(mm[2] + spb[ch])   + sb[ch];
                u1 += gelu_exact(mm[3] + spb[ch+1]) + sb[ch+1];
                *(float2*)(g_outn + i0e) = make_float2(v0, v1);
                *(float2*)(g_outn + i1e) = make_float2(u0, u1);
            }
        }
    }
}

// ---------------- 7) transpose NHWC -> (b,c,w,h) ----------------
__global__ void transpose_k(float* __restrict__ out0) {
    __shared__ float tile[32][33];
    int b = blockIdx.z, w = blockIdx.y, h0 = blockIdx.x * 32;
    int tx = threadIdx.x, ty = threadIdx.y;
    tile[ty][tx] = g_outn[(((size_t)b*HH + (h0 + ty))*WW + w)*32 + tx];
    __syncthreads();
    out0[(((size_t)b*CC + ty)*WW + w)*HH + h0 + tx] = tile[tx][ty];
}

// ---------------- launch ----------------
extern "C" void kernel_launch(void* const* d_in, const int* in_sizes, int n_in,
                              void* d_out, int out_size) {
    const float* x_fu   = (const float*)d_in[0];
    const float* x_msi  = (const float*)d_in[1];
    const float* x_hsi  = (const float*)d_in[2];
    const float* Wq     = (const float*)d_in[3];
    const float* Wk     = (const float*)d_in[4];
    const float* Wv     = (const float*)d_in[5];
    const float* proj_W = (const float*)d_in[6];
    const float* proj_b = (const float*)d_in[7];
    const float* pos1_W = (const float*)d_in[8];
    const float* pos1_b = (const float*)d_in[9];
    const float* pos2_W = (const float*)d_in[10];
    const float* pos2_b = (const float*)d_in[11];
    const float* ca_fc1 = (const float*)d_in[12];
    const float* ca_fc2 = (const float*)d_in[13];
    const float* sa_c1a = (const float*)d_in[14];
    const float* sa_c1b = (const float*)d_in[15];
    const float* sa_c2a = (const float*)d_in[16];
    const float* sa_c2b = (const float*)d_in[17];
    const float* sa_c3  = (const float*)d_in[18];
    const float* attn_W = (const float*)d_in[19];

    float* out0   = (float*)d_out;
    float* cm_out = out0 + IMG_ELEMS;
    float* sm_out = cm_out + BB*CC;

    cudaFuncSetAttribute(smask_k, cudaFuncAttributeMaxDynamicSharedMemorySize, SMASK_SMEM);
    cudaFuncSetAttribute(convm_k, cudaFuncAttributeMaxDynamicSharedMemorySize, CM_SMEM2);

    prep_k   <<<1, 256>>>(sa_c1a, sa_c1b, sa_c2a, sa_c2b, sa_c3);
    prep_wb_k<<<3, 256>>>(attn_W, pos1_W, pos2_W);
    stats1_k <<<dim3(256, BB), 256>>>(x_fu, x_hsi);
    red_k    <<<dim3(33, BB), 256>>>();
    stats2_k <<<BB, 256>>>(Wq, Wk, ca_fc1, ca_fc2, proj_W, cm_out);
    smask_k  <<<dim3(WW/SM_TW, HH/SM_TH, BB), 128, SMASK_SMEM>>>(x_msi, sm_out);
    vgated_k <<<dim3(HH, BB), 256>>>(x_fu, Wv);

    dim3 cg(WW/128, HH, BB);
    convm_k<<<cg, 128, CM_SMEM>>>(0, x_hsi, (const float*)nullptr, (const float*)nullptr);
    convm_k<<<cg, 128, CM_SMEM>>>(1, (const float*)nullptr, pos1_b, (const float*)nullptr);
    convm_k<<<cg, 128, CM_SMEM2>>>(2, (const float*)nullptr, pos2_b, proj_b);
    transpose_k<<<dim3(HH/32, WW, BB), dim3(32, 32)>>>(out0);
}